// round 8
// baseline (speedup 1.0000x reference)
#include <cuda_runtime.h>
#include <cuda_fp16.h>

#define N_NODES 100000
#define N_EDGES 1200000
#define FDIM 64
#define NB_SCAN ((N_NODES + 1023) / 1024)   // 98

// ---------------- scratch (device globals; no allocation allowed) -------------
__device__ int      g_is64;
__device__ int      g_degs[N_NODES];
__device__ int      g_degd[N_NODES];
__device__ int      g_rowptr[N_NODES + 1];
__device__ int      g_cursor[N_NODES];
__device__ int      g_bsum[NB_SCAN];
__device__ int2     g_edge[N_EDGES];
__device__ __half   g_xh [N_NODES * FDIM];
__device__ __half   g_t1h[N_NODES * FDIM];
__device__ __half   g_p2h[N_NODES * FDIM];
__device__ __half   g_hAh[N_NODES * FDIM];
__device__ __half   g_hBh[N_NODES * FDIM];
__device__ float    g_hA32[N_NODES * FDIM];
__device__ float    g_hB32[N_NODES * FDIM];
__device__ float    g_Wp[3][3 * FDIM * FDIM];
__device__ unsigned g_bar_count;
__device__ unsigned g_bar_gen;

// ---------------- init: zero degrees + dtype detection + barrier reset --------
__global__ void init_kernel(const int* __restrict__ ei32) {
    int i = blockIdx.x * blockDim.x + threadIdx.x;
    if (i < N_NODES) { g_degs[i] = 0; g_degd[i] = 0; }
    if (i == 0) {
        int odd_zero = 1;
        for (int k = 0; k < 512; k++)
            if (ei32[2 * k + 1] != 0) { odd_zero = 0; break; }
        g_is64 = odd_zero;
        g_bar_count = 0;
        g_bar_gen = 0;
    }
}

__device__ __forceinline__ void load_edge(const void* ei, int e, int& s, int& d) {
    if (g_is64) {
        const long long* p = (const long long*)ei;
        s = (int)p[e]; d = (int)p[N_EDGES + e];
    } else {
        const int* p = (const int*)ei;
        s = p[e]; d = p[N_EDGES + e];
    }
    if ((unsigned)s >= N_NODES || (unsigned)d >= N_NODES) { s = 0; d = 0; }
}

__global__ void count_kernel(const void* __restrict__ ei) {
    int e = blockIdx.x * blockDim.x + threadIdx.x;
    if (e >= N_EDGES) return;
    int s, d;
    load_edge(ei, e, s, d);
    atomicAdd(&g_degs[s], 1);
    atomicAdd(&g_degd[d], 1);
}

// ---- CSR build ---------------------------------------------------------------
__global__ __launch_bounds__(1024) void scan1_kernel() {
    __shared__ int s[1024];
    int tid = threadIdx.x;
    int i = blockIdx.x * 1024 + tid;
    int v = (i < N_NODES) ? g_degd[i] : 0;
    s[tid] = v;
    __syncthreads();
    for (int off = 1; off < 1024; off <<= 1) {
        int t = (tid >= off) ? s[tid - off] : 0;
        __syncthreads();
        s[tid] += t;
        __syncthreads();
    }
    int incl = s[tid];
    if (i < N_NODES) g_rowptr[i] = incl - v;
    if (tid == 1023) g_bsum[blockIdx.x] = incl;
}

__global__ __launch_bounds__(128) void scan2_kernel() {
    __shared__ int sh[128];
    int tid = threadIdx.x;
    int v = (tid < NB_SCAN) ? g_bsum[tid] : 0;
    sh[tid] = v;
    __syncthreads();
    for (int off = 1; off < 128; off <<= 1) {
        int t = (tid >= off) ? sh[tid - off] : 0;
        __syncthreads();
        sh[tid] += t;
        __syncthreads();
    }
    if (tid < NB_SCAN) g_bsum[tid] = sh[tid] - v;
    if (tid == 0) g_rowptr[N_NODES] = N_EDGES;
}

__global__ void scan3_kernel() {
    int i = blockIdx.x * blockDim.x + threadIdx.x;
    if (i >= N_NODES) return;
    int v = g_rowptr[i] + g_bsum[i >> 10];
    g_rowptr[i] = v;
    g_cursor[i] = v;
}

__global__ void fill_kernel(const void* __restrict__ ei) {
    int e = blockIdx.x * blockDim.x + threadIdx.x;
    if (e >= N_EDGES) return;
    int s, d;
    load_edge(ei, e, s, d);
    int pos = atomicAdd(&g_cursor[d], 1);
    int pd = g_degs[s] * g_degs[d];
    float nv = (pd > 0) ? -rsqrtf((float)pd) : 0.0f;
    g_edge[pos] = make_int2(s, __float_as_int(nv));
}

// ---- weight pre-transform: W0' = W0 - W2, W1' = W1, W2' = 2*W2 --------------
__global__ void wprep_kernel(const float* __restrict__ W) {
    int i = blockIdx.x * blockDim.x + threadIdx.x;
    if (i >= 3 * 3 * 4096) return;
    int layer = i / 12288, rem = i % 12288;
    int t = rem / 4096, idx = rem % 4096;
    const float* Wl = W + layer * 12288;
    float v;
    if (t == 0)      v = Wl[idx] - Wl[2 * 4096 + idx];
    else if (t == 1) v = Wl[4096 + idx];
    else             v = 2.0f * Wl[2 * 4096 + idx];
    g_Wp[layer][t * 4096 + idx] = v;
}

// ---- x -> fp16 copy ----------------------------------------------------------
__global__ void x2h_kernel(const float* __restrict__ x) {
    int i = blockIdx.x * blockDim.x + threadIdx.x;
    if (i >= N_NODES * FDIM / 4) return;
    float4 v = __ldg((const float4*)x + i);
    __half2 h0 = __floats2half2_rn(v.x, v.y);
    __half2 h1 = __floats2half2_rn(v.z, v.w);
    uint2 pk;
    pk.x = *(unsigned int*)&h0;
    pk.y = *(unsigned int*)&h1;
    ((uint2*)g_xh)[i] = pk;
}

// ---------------- grid-wide software barrier ----------------------------------
__device__ __forceinline__ void grid_barrier(int nblocks) {
    __syncthreads();
    if (threadIdx.x == 0) {
        __threadfence();
        unsigned gen = *(volatile unsigned*)&g_bar_gen;
        unsigned t = atomicAdd(&g_bar_count, 1u);
        if (t == (unsigned)nblocks - 1u) {
            g_bar_count = 0u;
            __threadfence();
            atomicAdd(&g_bar_gen, 1u);
        } else {
            while (*(volatile unsigned*)&g_bar_gen == gen) __nanosleep(64);
        }
        __threadfence();
    }
    __syncthreads();
}

// ---------------- pull phase (device fn): out[n] = sum norm * in[src] ---------
__device__ void pull_phase(const __half* __restrict__ in,
                           __half* __restrict__ out,
                           int gtid, int gstride) {
    for (int t = gtid; t < N_NODES * 8; t += gstride) {
        int node = t >> 3;
        int lane = t & 7;
        int e   = __ldg(&g_rowptr[node]);
        int end = __ldg(&g_rowptr[node + 1]);
        float acc[8];
#pragma unroll
        for (int j = 0; j < 8; j++) acc[j] = 0.f;

        if (e < end) {
            int2 ed[4];
            int last = end - 1;
#pragma unroll
            for (int i = 0; i < 4; i++)
                ed[i] = __ldg(&g_edge[min(e + i, last)]);

            while (true) {
                float n[4];
                uint4 v[4];
#pragma unroll
                for (int i = 0; i < 4; i++) {
                    bool valid = (e + i < end);
                    n[i] = valid ? __int_as_float(ed[i].y) : 0.f;
                    int src = valid ? ed[i].x : 0;
                    v[i] = __ldg((const uint4*)(in + src * FDIM + lane * 8));
                }
                int enext = e + 4;
                int2 ed2[4];
                bool more = (enext < end);
                if (more) {
#pragma unroll
                    for (int i = 0; i < 4; i++)
                        ed2[i] = __ldg(&g_edge[min(enext + i, last)]);
                }
#pragma unroll
                for (int i = 0; i < 4; i++) {
                    const __half2* hp = (const __half2*)&v[i];
#pragma unroll
                    for (int j = 0; j < 4; j++) {
                        float2 f = __half22float2(hp[j]);
                        acc[2 * j]     = fmaf(n[i], f.x, acc[2 * j]);
                        acc[2 * j + 1] = fmaf(n[i], f.y, acc[2 * j + 1]);
                    }
                }
                if (!more) break;
                e = enext;
#pragma unroll
                for (int i = 0; i < 4; i++) ed[i] = ed2[i];
            }
        }
        uint4 pk;
        __half2 h0 = __floats2half2_rn(acc[0], acc[1]);
        __half2 h1 = __floats2half2_rn(acc[2], acc[3]);
        __half2 h2 = __floats2half2_rn(acc[4], acc[5]);
        __half2 h3 = __floats2half2_rn(acc[6], acc[7]);
        pk.x = *(unsigned int*)&h0; pk.y = *(unsigned int*)&h1;
        pk.z = *(unsigned int*)&h2; pk.w = *(unsigned int*)&h3;
        *(uint4*)(out + node * FDIM + lane * 8) = pk;
    }
}

// ---------------- GEMM phase helpers ------------------------------------------
__device__ __forceinline__ void fma2(unsigned long long& acc,
                                     unsigned long long w,
                                     unsigned long long a) {
    asm("fma.rn.f32x2 %0, %1, %2, %0;" : "+l"(acc) : "l"(w), "l"(a));
}
__device__ __forceinline__ unsigned long long splat2(float f) {
    unsigned long long r;
    asm("mov.b64 %0, {%1, %1};" : "=l"(r) : "f"(f));
    return r;
}
__device__ __forceinline__ void h4_to_f4(uint2 u, float* f) {
    float2 lo = __half22float2(*(__half2*)&u.x);
    float2 hi = __half22float2(*(__half2*)&u.y);
    f[0] = lo.x; f[1] = lo.y; f[2] = hi.x; f[3] = hi.y;
}

// out32[r] = t0*W0' + t1h*W1' + p2h*W2' + bias (+skip), relu; optional fp16 copy
__device__ void gemm_phase(const float* __restrict__ t0,
                           const __half* __restrict__ t1h,
                           const __half* __restrict__ p2h,
                           const float* __restrict__ Wp,
                           const float* __restrict__ bias,
                           const float* __restrict__ skip,
                           float* __restrict__ out32,
                           __half* __restrict__ outh,
                           float* sW, int nblocks) {
    for (int i = threadIdx.x; i < 3 * FDIM * FDIM / 4; i += 256)
        ((float4*)sW)[i] = ((const float4*)Wp)[i];
    __syncthreads();

    int rg = threadIdx.x >> 2;
    int q  = threadIdx.x & 3;
    int jb = q * 16;

    float bia[16];
#pragma unroll
    for (int j = 0; j < 16; j++) bia[j] = bias[jb + j];

    const int ntiles = (N_NODES + 127) / 128;
    for (int tile = blockIdx.x; tile < ntiles; tile += nblocks) {
        int base = tile * 128;
        int rA = base + rg;
        int rB = base + rg + 64;
        bool okA = rA < N_NODES, okB = rB < N_NODES;
        if (!okA) continue;

        unsigned long long accA[8], accB[8];
#pragma unroll
        for (int i = 0; i < 8; i++) { accA[i] = 0ULL; accB[i] = 0ULL; }

#pragma unroll 2
        for (int kk = 0; kk < FDIM; kk += 4) {
            float4 xa0 = __ldg((const float4*)(t0 + rA * FDIM + kk));
            uint2  ua1 = __ldg((const uint2*)(t1h + rA * FDIM + kk));
            uint2  ua2 = __ldg((const uint2*)(p2h + rA * FDIM + kk));
            float4 xb0 = make_float4(0.f, 0.f, 0.f, 0.f);
            uint2  ub1 = make_uint2(0u, 0u), ub2 = make_uint2(0u, 0u);
            if (okB) {
                xb0 = __ldg((const float4*)(t0 + rB * FDIM + kk));
                ub1 = __ldg((const uint2*)(t1h + rB * FDIM + kk));
                ub2 = __ldg((const uint2*)(p2h + rB * FDIM + kk));
            }
            float fa0[4] = {xa0.x, xa0.y, xa0.z, xa0.w};
            float fb0[4] = {xb0.x, xb0.y, xb0.z, xb0.w};
            float fa1[4], fa2[4], fb1[4], fb2[4];
            h4_to_f4(ua1, fa1); h4_to_f4(ua2, fa2);
            h4_to_f4(ub1, fb1); h4_to_f4(ub2, fb2);
#pragma unroll
            for (int u = 0; u < 4; u++) {
                int k = kk + u;
                const ulonglong2* w0 = (const ulonglong2*)(sW + k * FDIM + jb);
                const ulonglong2* w1 = (const ulonglong2*)(sW + 4096 + k * FDIM + jb);
                const ulonglong2* w2 = (const ulonglong2*)(sW + 8192 + k * FDIM + jb);
                {
                    unsigned long long sA = splat2(fa0[u]), sB = splat2(fb0[u]);
#pragma unroll
                    for (int p = 0; p < 4; p++) {
                        ulonglong2 w = w0[p];
                        fma2(accA[2 * p], w.x, sA); fma2(accA[2 * p + 1], w.y, sA);
                        fma2(accB[2 * p], w.x, sB); fma2(accB[2 * p + 1], w.y, sB);
                    }
                }
                {
                    unsigned long long sA = splat2(fa1[u]), sB = splat2(fb1[u]);
#pragma unroll
                    for (int p = 0; p < 4; p++) {
                        ulonglong2 w = w1[p];
                        fma2(accA[2 * p], w.x, sA); fma2(accA[2 * p + 1], w.y, sA);
                        fma2(accB[2 * p], w.x, sB); fma2(accB[2 * p + 1], w.y, sB);
                    }
                }
                {
                    unsigned long long sA = splat2(fa2[u]), sB = splat2(fb2[u]);
#pragma unroll
                    for (int p = 0; p < 4; p++) {
                        ulonglong2 w = w2[p];
                        fma2(accA[2 * p], w.x, sA); fma2(accA[2 * p + 1], w.y, sA);
                        fma2(accB[2 * p], w.x, sB); fma2(accB[2 * p + 1], w.y, sB);
                    }
                }
            }
        }

#pragma unroll
        for (int rr = 0; rr < 2; rr++) {
            if (rr && !okB) break;
            int r = rr ? rB : rA;
            unsigned long long* acc = rr ? accB : accA;
            float o[16];
#pragma unroll
            for (int i = 0; i < 8; i++) {
                float f0, f1;
                asm("mov.b64 {%0, %1}, %2;" : "=f"(f0), "=f"(f1) : "l"(acc[i]));
                o[2 * i] = f0; o[2 * i + 1] = f1;
            }
#pragma unroll
            for (int j = 0; j < 16; j++) {
                float v = o[j] + bia[j];
                if (skip) v += skip[r * FDIM + jb + j];
                o[j] = fmaxf(v, 0.f);
            }
#pragma unroll
            for (int p = 0; p < 4; p++)
                *(float4*)(out32 + r * FDIM + jb + 4 * p) =
                    make_float4(o[4*p], o[4*p+1], o[4*p+2], o[4*p+3]);
            if (outh) {
#pragma unroll
                for (int p = 0; p < 2; p++) {
                    uint4 pk;
                    __half2 h0 = __floats2half2_rn(o[8*p+0], o[8*p+1]);
                    __half2 h1 = __floats2half2_rn(o[8*p+2], o[8*p+3]);
                    __half2 h2 = __floats2half2_rn(o[8*p+4], o[8*p+5]);
                    __half2 h3 = __floats2half2_rn(o[8*p+6], o[8*p+7]);
                    pk.x = *(unsigned int*)&h0; pk.y = *(unsigned int*)&h1;
                    pk.z = *(unsigned int*)&h2; pk.w = *(unsigned int*)&h3;
                    *(uint4*)(outh + r * FDIM + jb + 8 * p) = pk;
                }
            }
        }
    }
}

// ---------------- persistent fused compute kernel -----------------------------
__global__ __launch_bounds__(256, 2) void fused_kernel(
    const float* __restrict__ x, const float* __restrict__ b,
    float* __restrict__ out, int nblocks) {
    __shared__ float sW[3 * FDIM * FDIM];  // 48 KB
    int gtid = blockIdx.x * 256 + threadIdx.x;
    int gstride = nblocks * 256;

    // layer 0
    pull_phase(g_xh, g_t1h, gtid, gstride);
    grid_barrier(nblocks);
    pull_phase(g_t1h, g_p2h, gtid, gstride);
    grid_barrier(nblocks);
    gemm_phase(x, g_t1h, g_p2h, g_Wp[0], b, nullptr, g_hA32, g_hAh, sW, nblocks);
    grid_barrier(nblocks);
    // layer 1
    pull_phase(g_hAh, g_t1h, gtid, gstride);
    grid_barrier(nblocks);
    pull_phase(g_t1h, g_p2h, gtid, gstride);
    grid_barrier(nblocks);
    gemm_phase(g_hA32, g_t1h, g_p2h, g_Wp[1], b + FDIM, g_hA32,
               g_hB32, g_hBh, sW, nblocks);
    grid_barrier(nblocks);
    // layer 2
    pull_phase(g_hBh, g_t1h, gtid, gstride);
    grid_barrier(nblocks);
    pull_phase(g_t1h, g_p2h, gtid, gstride);
    grid_barrier(nblocks);
    gemm_phase(g_hB32, g_t1h, g_p2h, g_Wp[2], b + 2 * FDIM, g_hB32,
               out, nullptr, sW, nblocks);
}

// ---------------- launch orchestration ---------------------------------------
static inline int cdiv(long long a, long long b) { return (int)((a + b - 1) / b); }

extern "C" void kernel_launch(void* const* d_in, const int* in_sizes, int n_in,
                              void* d_out, int out_size) {
    const float* x  = (const float*)d_in[0];
    const void*  ei = d_in[1];
    const float* W  = (const float*)d_in[2];
    const float* b  = (const float*)d_in[3];
    float*       out = (float*)d_out;

    // ---- graph prep (8 launches) ----
    init_kernel<<<cdiv(N_NODES, 256), 256>>>((const int*)ei);
    count_kernel<<<cdiv(N_EDGES, 256), 256>>>(ei);
    scan1_kernel<<<NB_SCAN, 1024>>>();
    scan2_kernel<<<1, 128>>>();
    scan3_kernel<<<cdiv(N_NODES, 256), 256>>>();
    fill_kernel<<<cdiv(N_EDGES, 256), 256>>>(ei);
    wprep_kernel<<<cdiv(3 * 3 * 4096, 256), 256>>>(W);
    x2h_kernel<<<cdiv(N_NODES * FDIM / 4, 256), 256>>>(x);

    // ---- persistent fused compute (1 launch, co-resident grid) ----
    int dev = 0, nsm = 148, nb_per_sm = 0;
    cudaGetDevice(&dev);
    cudaDeviceGetAttribute(&nsm, cudaDevAttrMultiProcessorCount, dev);
    cudaOccupancyMaxActiveBlocksPerMultiprocessor(&nb_per_sm, fused_kernel,
                                                  256, 0);
    if (nb_per_sm < 1) nb_per_sm = 1;
    int nblocks = nsm * nb_per_sm;
    fused_kernel<<<nblocks, 256>>>(x, b, out, nblocks);
}

// round 10
// speedup vs baseline: 1.0709x; 1.0709x over previous
#include <cuda_runtime.h>
#include <cuda_fp16.h>

#define N_NODES 100000
#define N_EDGES 1200000
#define FDIM 64
#define NB_SCAN ((N_NODES + 1023) / 1024)   // 98

// ---------------- scratch (device globals; no allocation allowed) -------------
__device__ int      g_is64;
__device__ int      g_degs[N_NODES];
__device__ int      g_degd[N_NODES];
__device__ int      g_rowptr[N_NODES + 1];
__device__ int      g_cursor[N_NODES];
__device__ int      g_bsum[NB_SCAN];
__device__ int2     g_edge[N_EDGES];
__device__ __half   g_xh [N_NODES * FDIM];
__device__ __half   g_t1h[N_NODES * FDIM];
__device__ __half   g_p2h[N_NODES * FDIM];
__device__ __half   g_hAh[N_NODES * FDIM];
__device__ __half   g_hBh[N_NODES * FDIM];
__device__ float    g_hA32[N_NODES * FDIM];
__device__ float    g_hB32[N_NODES * FDIM];
__device__ float    g_Wp[3][3 * FDIM * FDIM];
__device__ unsigned g_bar_count;
__device__ unsigned g_bar_gen;

// ---------------- launch 1: zero degrees + dtype detect + barrier reset -------
__global__ void init_kernel(const int* __restrict__ ei32) {
    int i = blockIdx.x * blockDim.x + threadIdx.x;
    if (i < N_NODES) { g_degs[i] = 0; g_degd[i] = 0; }
    if (i == 0) {
        int odd_zero = 1;
        for (int k = 0; k < 512; k++)
            if (ei32[2 * k + 1] != 0) { odd_zero = 0; break; }
        g_is64 = odd_zero;
        g_bar_count = 0;
        g_bar_gen = 0;
    }
}

__device__ __forceinline__ void load_edge(const void* ei, int e, int& s, int& d) {
    if (g_is64) {
        const long long* p = (const long long*)ei;
        s = (int)p[e]; d = (int)p[N_EDGES + e];
    } else {
        const int* p = (const int*)ei;
        s = p[e]; d = p[N_EDGES + e];
    }
    if ((unsigned)s >= N_NODES || (unsigned)d >= N_NODES) { s = 0; d = 0; }
}

// ---------------- launch 2: degree histogram ----------------------------------
__global__ void count_kernel(const void* __restrict__ ei) {
    int e = blockIdx.x * blockDim.x + threadIdx.x;
    if (e >= N_EDGES) return;
    int s, d;
    load_edge(ei, e, s, d);
    atomicAdd(&g_degs[s], 1);
    atomicAdd(&g_degd[d], 1);
}

// ---------------- launch 3: per-block scan of in-degrees ----------------------
__global__ __launch_bounds__(1024) void scan1_kernel() {
    __shared__ int s[1024];
    int tid = threadIdx.x;
    int i = blockIdx.x * 1024 + tid;
    int v = (i < N_NODES) ? g_degd[i] : 0;
    s[tid] = v;
    __syncthreads();
    for (int off = 1; off < 1024; off <<= 1) {
        int t = (tid >= off) ? s[tid - off] : 0;
        __syncthreads();
        s[tid] += t;
        __syncthreads();
    }
    int incl = s[tid];
    if (i < N_NODES) g_rowptr[i] = incl - v;
    if (tid == 1023) g_bsum[blockIdx.x] = incl;
}

// ---------------- grid-wide software barrier ----------------------------------
__device__ __forceinline__ void grid_barrier(int nblocks) {
    __syncthreads();
    if (threadIdx.x == 0) {
        __threadfence();
        unsigned gen = *(volatile unsigned*)&g_bar_gen;
        unsigned t = atomicAdd(&g_bar_count, 1u);
        if (t == (unsigned)nblocks - 1u) {
            g_bar_count = 0u;
            __threadfence();
            atomicAdd(&g_bar_gen, 1u);
        } else {
            while (*(volatile unsigned*)&g_bar_gen == gen) __nanosleep(64);
        }
        __threadfence();
    }
    __syncthreads();
}

// ---------------- pull phase: out[n] = sum norm * in[src], fp16 rows ----------
__device__ void pull_phase(const __half* __restrict__ in,
                           __half* __restrict__ out,
                           int gtid, int gstride) {
    for (int t = gtid; t < N_NODES * 8; t += gstride) {
        int node = t >> 3;
        int lane = t & 7;
        int e   = __ldg(&g_rowptr[node]);
        int end = __ldg(&g_rowptr[node + 1]);
        float acc[8];
#pragma unroll
        for (int j = 0; j < 8; j++) acc[j] = 0.f;

        if (e < end) {
            int2 ed[4];
            int last = end - 1;
#pragma unroll
            for (int i = 0; i < 4; i++)
                ed[i] = __ldg(&g_edge[min(e + i, last)]);

            while (true) {
                float n[4];
                uint4 v[4];
#pragma unroll
                for (int i = 0; i < 4; i++) {
                    bool valid = (e + i < end);
                    n[i] = valid ? __int_as_float(ed[i].y) : 0.f;
                    int src = valid ? ed[i].x : 0;
                    v[i] = __ldg((const uint4*)(in + src * FDIM + lane * 8));
                }
                int enext = e + 4;
                int2 ed2[4];
                bool more = (enext < end);
                if (more) {
#pragma unroll
                    for (int i = 0; i < 4; i++)
                        ed2[i] = __ldg(&g_edge[min(enext + i, last)]);
                }
#pragma unroll
                for (int i = 0; i < 4; i++) {
                    const __half2* hp = (const __half2*)&v[i];
#pragma unroll
                    for (int j = 0; j < 4; j++) {
                        float2 f = __half22float2(hp[j]);
                        acc[2 * j]     = fmaf(n[i], f.x, acc[2 * j]);
                        acc[2 * j + 1] = fmaf(n[i], f.y, acc[2 * j + 1]);
                    }
                }
                if (!more) break;
                e = enext;
#pragma unroll
                for (int i = 0; i < 4; i++) ed[i] = ed2[i];
            }
        }
        uint4 pk;
        __half2 h0 = __floats2half2_rn(acc[0], acc[1]);
        __half2 h1 = __floats2half2_rn(acc[2], acc[3]);
        __half2 h2 = __floats2half2_rn(acc[4], acc[5]);
        __half2 h3 = __floats2half2_rn(acc[6], acc[7]);
        pk.x = *(unsigned int*)&h0; pk.y = *(unsigned int*)&h1;
        pk.z = *(unsigned int*)&h2; pk.w = *(unsigned int*)&h3;
        *(uint4*)(out + node * FDIM + lane * 8) = pk;
    }
}

// ---------------- GEMM helpers -------------------------------------------------
__device__ __forceinline__ void fma2(unsigned long long& acc,
                                     unsigned long long w,
                                     unsigned long long a) {
    asm("fma.rn.f32x2 %0, %1, %2, %0;" : "+l"(acc) : "l"(w), "l"(a));
}
__device__ __forceinline__ unsigned long long splat2(float f) {
    unsigned long long r;
    asm("mov.b64 %0, {%1, %1};" : "=l"(r) : "f"(f));
    return r;
}
__device__ __forceinline__ void h4_to_f4(uint2 u, float* f) {
    float2 lo = __half22float2(*(__half2*)&u.x);
    float2 hi = __half22float2(*(__half2*)&u.y);
    f[0] = lo.x; f[1] = lo.y; f[2] = hi.x; f[3] = hi.y;
}

// GEMM phase: 512 threads = 64 row-slots x 8 j-groups (8 outputs each),
// 2 rows per thread (tile = 128 rows). Low reg pressure (acc = 16 floats).
__device__ void gemm_phase(const float* __restrict__ t0,
                           const __half* __restrict__ t1h,
                           const __half* __restrict__ p2h,
                           const float* __restrict__ Wp,
                           const float* __restrict__ bias,
                           const float* __restrict__ skip,
                           float* __restrict__ out32,
                           __half* __restrict__ outh,
                           float* sW, int nblocks) {
    for (int i = threadIdx.x; i < 3 * FDIM * FDIM / 4; i += 512)
        ((float4*)sW)[i] = ((const float4*)Wp)[i];
    __syncthreads();

    int rg = threadIdx.x >> 3;     // 0..63
    int q  = threadIdx.x & 7;      // 0..7
    int jb = q * 8;

    float bia[8];
#pragma unroll
    for (int j = 0; j < 8; j++) bia[j] = bias[jb + j];

    const int ntiles = (N_NODES + 127) / 128;
    for (int tile = blockIdx.x; tile < ntiles; tile += nblocks) {
        int base = tile * 128;
        int rA = base + rg;
        int rB = base + rg + 64;
        bool okA = rA < N_NODES, okB = rB < N_NODES;
        if (!okA) continue;

        unsigned long long accA[4], accB[4];
#pragma unroll
        for (int i = 0; i < 4; i++) { accA[i] = 0ULL; accB[i] = 0ULL; }

#pragma unroll 2
        for (int kk = 0; kk < FDIM; kk += 4) {
            float4 xa0 = __ldg((const float4*)(t0 + rA * FDIM + kk));
            uint2  ua1 = __ldg((const uint2*)(t1h + rA * FDIM + kk));
            uint2  ua2 = __ldg((const uint2*)(p2h + rA * FDIM + kk));
            float4 xb0 = make_float4(0.f, 0.f, 0.f, 0.f);
            uint2  ub1 = make_uint2(0u, 0u), ub2 = make_uint2(0u, 0u);
            if (okB) {
                xb0 = __ldg((const float4*)(t0 + rB * FDIM + kk));
                ub1 = __ldg((const uint2*)(t1h + rB * FDIM + kk));
                ub2 = __ldg((const uint2*)(p2h + rB * FDIM + kk));
            }
            float fa0[4] = {xa0.x, xa0.y, xa0.z, xa0.w};
            float fb0[4] = {xb0.x, xb0.y, xb0.z, xb0.w};
            float fa1[4], fa2[4], fb1[4], fb2[4];
            h4_to_f4(ua1, fa1); h4_to_f4(ua2, fa2);
            h4_to_f4(ub1, fb1); h4_to_f4(ub2, fb2);
#pragma unroll
            for (int u = 0; u < 4; u++) {
                int k = kk + u;
                const ulonglong2* w0 = (const ulonglong2*)(sW + k * FDIM + jb);
                const ulonglong2* w1 = (const ulonglong2*)(sW + 4096 + k * FDIM + jb);
                const ulonglong2* w2 = (const ulonglong2*)(sW + 8192 + k * FDIM + jb);
                {
                    ulonglong2 w = w0[0], wb = w0[1];
                    unsigned long long sA = splat2(fa0[u]), sB = splat2(fb0[u]);
                    fma2(accA[0], w.x, sA);  fma2(accA[1], w.y, sA);
                    fma2(accA[2], wb.x, sA); fma2(accA[3], wb.y, sA);
                    fma2(accB[0], w.x, sB);  fma2(accB[1], w.y, sB);
                    fma2(accB[2], wb.x, sB); fma2(accB[3], wb.y, sB);
                }
                {
                    ulonglong2 w = w1[0], wb = w1[1];
                    unsigned long long sA = splat2(fa1[u]), sB = splat2(fb1[u]);
                    fma2(accA[0], w.x, sA);  fma2(accA[1], w.y, sA);
                    fma2(accA[2], wb.x, sA); fma2(accA[3], wb.y, sA);
                    fma2(accB[0], w.x, sB);  fma2(accB[1], w.y, sB);
                    fma2(accB[2], wb.x, sB); fma2(accB[3], wb.y, sB);
                }
                {
                    ulonglong2 w = w2[0], wb = w2[1];
                    unsigned long long sA = splat2(fa2[u]), sB = splat2(fb2[u]);
                    fma2(accA[0], w.x, sA);  fma2(accA[1], w.y, sA);
                    fma2(accA[2], wb.x, sA); fma2(accA[3], wb.y, sA);
                    fma2(accB[0], w.x, sB);  fma2(accB[1], w.y, sB);
                    fma2(accB[2], wb.x, sB); fma2(accB[3], wb.y, sB);
                }
            }
        }

#pragma unroll
        for (int rr = 0; rr < 2; rr++) {
            if (rr && !okB) break;
            int r = rr ? rB : rA;
            unsigned long long* acc = rr ? accB : accA;
            float o[8];
#pragma unroll
            for (int i = 0; i < 4; i++) {
                float f0, f1;
                asm("mov.b64 {%0, %1}, %2;" : "=f"(f0), "=f"(f1) : "l"(acc[i]));
                o[2 * i] = f0; o[2 * i + 1] = f1;
            }
#pragma unroll
            for (int j = 0; j < 8; j++) {
                float v = o[j] + bia[j];
                if (skip) v += skip[r * FDIM + jb + j];
                o[j] = fmaxf(v, 0.f);
            }
            *(float4*)(out32 + r * FDIM + jb)     =
                make_float4(o[0], o[1], o[2], o[3]);
            *(float4*)(out32 + r * FDIM + jb + 4) =
                make_float4(o[4], o[5], o[6], o[7]);
            if (outh) {
                uint4 pk;
                __half2 h0 = __floats2half2_rn(o[0], o[1]);
                __half2 h1 = __floats2half2_rn(o[2], o[3]);
                __half2 h2 = __floats2half2_rn(o[4], o[5]);
                __half2 h3 = __floats2half2_rn(o[6], o[7]);
                pk.x = *(unsigned int*)&h0; pk.y = *(unsigned int*)&h1;
                pk.z = *(unsigned int*)&h2; pk.w = *(unsigned int*)&h3;
                *(uint4*)(outh + r * FDIM + jb) = pk;
            }
        }
    }
}

// ---------------- launch 4: persistent fused prep+compute ---------------------
// NOTE: total static smem must stay <= 48 KB. The 128-int scan2 scratch is
// overlaid onto sW — the scan completes and its results are consumed (scan3)
// behind grid barriers before gemm_phase first writes sW.
__global__ __launch_bounds__(512, 2) void fused_kernel(
    const float* __restrict__ x, const void* __restrict__ ei,
    const float* __restrict__ W, const float* __restrict__ b,
    float* __restrict__ out, int nblocks) {
    __shared__ float sW[3 * FDIM * FDIM];  // 48 KB (also scan2 scratch)
    int tid = threadIdx.x;
    int gtid = blockIdx.x * 512 + tid;
    int gstride = nblocks * 512;

    // ---- scan2 (block 0 only; scratch overlaid on sW) ----
    if (blockIdx.x == 0) {
        int* sh = (int*)sW;
        int v = 0;
        if (tid < 128) {
            v = (tid < NB_SCAN) ? g_bsum[tid] : 0;
            sh[tid] = v;
        }
        __syncthreads();
        for (int off = 1; off < 128; off <<= 1) {
            int t2 = 0;
            if (tid < 128 && tid >= off) t2 = sh[tid - off];
            __syncthreads();
            if (tid < 128) sh[tid] += t2;
            __syncthreads();
        }
        if (tid < NB_SCAN) g_bsum[tid] = sh[tid] - v;
        if (tid == 0) g_rowptr[N_NODES] = N_EDGES;
    }
    grid_barrier(nblocks);

    // ---- scan3: finalize rowptr + cursor ----
    for (int i = gtid; i < N_NODES; i += gstride) {
        int v = g_rowptr[i] + g_bsum[i >> 10];
        g_rowptr[i] = v;
        g_cursor[i] = v;
    }
    grid_barrier(nblocks);

    // ---- fill CSR + weight transform + x->fp16 (independent work) ----
    for (int e = gtid; e < N_EDGES; e += gstride) {
        int s, d;
        load_edge(ei, e, s, d);
        int pos = atomicAdd(&g_cursor[d], 1);
        int pd = g_degs[s] * g_degs[d];
        float nv = (pd > 0) ? -rsqrtf((float)pd) : 0.0f;
        g_edge[pos] = make_int2(s, __float_as_int(nv));
    }
    for (int i = gtid; i < 3 * 3 * 4096; i += gstride) {
        int layer = i / 12288, rem = i % 12288;
        int t = rem / 4096, idx = rem % 4096;
        const float* Wl = W + layer * 12288;
        float v;
        if (t == 0)      v = Wl[idx] - Wl[2 * 4096 + idx];
        else if (t == 1) v = Wl[4096 + idx];
        else             v = 2.0f * Wl[2 * 4096 + idx];
        g_Wp[layer][t * 4096 + idx] = v;
    }
    for (int i = gtid; i < N_NODES * FDIM / 4; i += gstride) {
        float4 v = __ldg((const float4*)x + i);
        __half2 h0 = __floats2half2_rn(v.x, v.y);
        __half2 h1 = __floats2half2_rn(v.z, v.w);
        uint2 pk;
        pk.x = *(unsigned int*)&h0;
        pk.y = *(unsigned int*)&h1;
        ((uint2*)g_xh)[i] = pk;
    }
    grid_barrier(nblocks);

    // ---- layer 0 ----
    pull_phase(g_xh, g_t1h, gtid, gstride);
    grid_barrier(nblocks);
    pull_phase(g_t1h, g_p2h, gtid, gstride);
    grid_barrier(nblocks);
    gemm_phase(x, g_t1h, g_p2h, g_Wp[0], b, nullptr, g_hA32, g_hAh, sW, nblocks);
    grid_barrier(nblocks);
    // ---- layer 1 ----
    pull_phase(g_hAh, g_t1h, gtid, gstride);
    grid_barrier(nblocks);
    pull_phase(g_t1h, g_p2h, gtid, gstride);
    grid_barrier(nblocks);
    gemm_phase(g_hA32, g_t1h, g_p2h, g_Wp[1], b + FDIM, g_hA32,
               g_hB32, g_hBh, sW, nblocks);
    grid_barrier(nblocks);
    // ---- layer 2 ----
    pull_phase(g_hBh, g_t1h, gtid, gstride);
    grid_barrier(nblocks);
    pull_phase(g_t1h, g_p2h, gtid, gstride);
    grid_barrier(nblocks);
    gemm_phase(g_hB32, g_t1h, g_p2h, g_Wp[2], b + 2 * FDIM, g_hB32,
               out, nullptr, sW, nblocks);
}

// ---------------- launch orchestration ---------------------------------------
static inline int cdiv(long long a, long long b) { return (int)((a + b - 1) / b); }

extern "C" void kernel_launch(void* const* d_in, const int* in_sizes, int n_in,
                              void* d_out, int out_size) {
    const float* x  = (const float*)d_in[0];
    const void*  ei = d_in[1];
    const float* W  = (const float*)d_in[2];
    const float* b  = (const float*)d_in[3];
    float*       out = (float*)d_out;

    // launches 1-3: init, degree count, per-chunk scan
    init_kernel<<<cdiv(N_NODES, 256), 256>>>((const int*)ei);
    count_kernel<<<cdiv(N_EDGES, 256), 256>>>(ei);
    scan1_kernel<<<NB_SCAN, 1024>>>();

    // launch 4: everything else, persistent + grid barriers
    int dev = 0, nsm = 148, nb_per_sm = 0;
    cudaGetDevice(&dev);
    cudaDeviceGetAttribute(&nsm, cudaDevAttrMultiProcessorCount, dev);
    cudaOccupancyMaxActiveBlocksPerMultiprocessor(&nb_per_sm, fused_kernel,
                                                  512, 0);
    if (nb_per_sm < 1) nb_per_sm = 1;
    int nblocks = nsm * nb_per_sm;
    fused_kernel<<<nblocks, 512>>>(x, ei, W, b, out, nblocks);
}

// round 11
// speedup vs baseline: 1.6721x; 1.5614x over previous
#include <cuda_runtime.h>
#include <cuda_fp16.h>

#define N_NODES 100000
#define N_EDGES 1200000
#define FDIM 64
#define NB_SCAN ((N_NODES + 1023) / 1024)   // 98

// ---------------- scratch (device globals; no allocation allowed) -------------
__device__ int      g_is64;
__device__ int      g_degs[N_NODES];
__device__ int      g_degd[N_NODES];
__device__ int      g_rowptr[N_NODES + 1];
__device__ int      g_cursor[N_NODES];
__device__ int      g_bsum[NB_SCAN];
__device__ int4     g_edge4[N_EDGES / 2];    // (src,norm) pairs, 16B-aligned
__device__ __half   g_xh [N_NODES * FDIM];
__device__ __half   g_t1h[N_NODES * FDIM];
__device__ __half   g_p2h[N_NODES * FDIM];
__device__ __half   g_hAh[N_NODES * FDIM];
__device__ __half   g_hBh[N_NODES * FDIM];
__device__ float    g_hA32[N_NODES * FDIM];
__device__ float    g_hB32[N_NODES * FDIM];
__device__ float    g_Wp[3][3 * FDIM * FDIM];
__device__ unsigned g_bar_count;
__device__ unsigned g_bar_gen;

// ---------------- launch 1: zero degrees + dtype detect + barrier reset -------
__global__ void init_kernel(const int* __restrict__ ei32) {
    int i = blockIdx.x * blockDim.x + threadIdx.x;
    if (i < N_NODES) { g_degs[i] = 0; g_degd[i] = 0; }
    if (i == 0) {
        int odd_zero = 1;
        for (int k = 0; k < 512; k++)
            if (ei32[2 * k + 1] != 0) { odd_zero = 0; break; }
        g_is64 = odd_zero;
        g_bar_count = 0;
        g_bar_gen = 0;
    }
}

__device__ __forceinline__ void load_edge(const void* ei, int e, int& s, int& d) {
    if (g_is64) {
        const long long* p = (const long long*)ei;
        s = (int)p[e]; d = (int)p[N_EDGES + e];
    } else {
        const int* p = (const int*)ei;
        s = p[e]; d = p[N_EDGES + e];
    }
    if ((unsigned)s >= N_NODES || (unsigned)d >= N_NODES) { s = 0; d = 0; }
}

// ---------------- launch 2: degree histogram ----------------------------------
__global__ void count_kernel(const void* __restrict__ ei) {
    int e = blockIdx.x * blockDim.x + threadIdx.x;
    if (e >= N_EDGES) return;
    int s, d;
    load_edge(ei, e, s, d);
    atomicAdd(&g_degs[s], 1);
    atomicAdd(&g_degd[d], 1);
}

// ---------------- launch 3: per-block scan of in-degrees ----------------------
__global__ __launch_bounds__(1024) void scan1_kernel() {
    __shared__ int s[1024];
    int tid = threadIdx.x;
    int i = blockIdx.x * 1024 + tid;
    int v = (i < N_NODES) ? g_degd[i] : 0;
    s[tid] = v;
    __syncthreads();
    for (int off = 1; off < 1024; off <<= 1) {
        int t = (tid >= off) ? s[tid - off] : 0;
        __syncthreads();
        s[tid] += t;
        __syncthreads();
    }
    int incl = s[tid];
    if (i < N_NODES) g_rowptr[i] = incl - v;
    if (tid == 1023) g_bsum[blockIdx.x] = incl;
}

// ---------------- grid-wide software barrier ----------------------------------
__device__ __forceinline__ void grid_barrier(int nblocks) {
    __syncthreads();
    if (threadIdx.x == 0) {
        __threadfence();
        unsigned gen = *(volatile unsigned*)&g_bar_gen;
        unsigned t = atomicAdd(&g_bar_count, 1u);
        if (t == (unsigned)nblocks - 1u) {
            g_bar_count = 0u;
            __threadfence();
            atomicAdd(&g_bar_gen, 1u);
        } else {
            while (*(volatile unsigned*)&g_bar_gen == gen) __nanosleep(64);
        }
        __threadfence();
    }
    __syncthreads();
}

// ---------------- pull phase: out[n] = sum norm * in[src], fp16 rows ----------
// 8 lanes per node, 16B per lane. Edge descriptors loaded 2-at-a-time as int4
// (16B aligned) — 2 LDG.128 per 4-edge batch instead of 8 LDG.64.
__device__ void pull_phase(const __half* __restrict__ in,
                           __half* __restrict__ out,
                           int gtid, int gstride) {
    for (int t = gtid; t < N_NODES * 8; t += gstride) {
        int node = t >> 3;
        int lane = t & 7;
        int e0  = __ldg(&g_rowptr[node]);
        int end = __ldg(&g_rowptr[node + 1]);
        float acc[8];
#pragma unroll
        for (int j = 0; j < 8; j++) acc[j] = 0.f;

        if (e0 < end) {
            for (int base = e0 & ~1; base < end; base += 4) {
                int4 qa = __ldg(&g_edge4[min(base,     N_EDGES - 2) >> 1]);
                int4 qb = __ldg(&g_edge4[min(base + 2, N_EDGES - 2) >> 1]);
                int  srcs[4] = {qa.x, qa.z, qb.x, qb.z};
                int  nrm [4] = {qa.y, qa.w, qb.y, qb.w};
                float nf[4];
                uint4 v[4];
#pragma unroll
                for (int j = 0; j < 4; j++) {
                    int idx = base + j;
                    bool valid = (idx >= e0) && (idx < end);
                    nf[j] = valid ? __int_as_float(nrm[j]) : 0.f;
                    int src = valid ? srcs[j] : 0;
                    v[j] = __ldg((const uint4*)(in + src * FDIM + lane * 8));
                }
#pragma unroll
                for (int j = 0; j < 4; j++) {
                    const __half2* hp = (const __half2*)&v[j];
#pragma unroll
                    for (int p = 0; p < 4; p++) {
                        float2 f = __half22float2(hp[p]);
                        acc[2 * p]     = fmaf(nf[j], f.x, acc[2 * p]);
                        acc[2 * p + 1] = fmaf(nf[j], f.y, acc[2 * p + 1]);
                    }
                }
            }
        }
        uint4 pk;
        __half2 h0 = __floats2half2_rn(acc[0], acc[1]);
        __half2 h1 = __floats2half2_rn(acc[2], acc[3]);
        __half2 h2 = __floats2half2_rn(acc[4], acc[5]);
        __half2 h3 = __floats2half2_rn(acc[6], acc[7]);
        pk.x = *(unsigned int*)&h0; pk.y = *(unsigned int*)&h1;
        pk.z = *(unsigned int*)&h2; pk.w = *(unsigned int*)&h3;
        *(uint4*)(out + node * FDIM + lane * 8) = pk;
    }
}

// ---------------- GEMM helpers -------------------------------------------------
__device__ __forceinline__ void fma2(unsigned long long& acc,
                                     unsigned long long w,
                                     unsigned long long a) {
    asm("fma.rn.f32x2 %0, %1, %2, %0;" : "+l"(acc) : "l"(w), "l"(a));
}
__device__ __forceinline__ unsigned long long splat2(float f) {
    unsigned long long r;
    asm("mov.b64 %0, {%1, %1};" : "=l"(r) : "f"(f));
    return r;
}

// GEMM phase: 512 threads = 32 row-slots x 16 j-groups (4 outputs each),
// 4 rows per thread (tile = 128 rows). Per k only 3 LDS.128 for 24 FMA2:
// half the weight-smem traffic of the 2-row variant.
__device__ void gemm_phase(const float* __restrict__ t0,
                           const __half* __restrict__ t1h,
                           const __half* __restrict__ p2h,
                           const float* __restrict__ Wp,
                           const float* __restrict__ bias,
                           const float* __restrict__ skip,
                           float* __restrict__ out32,
                           __half* __restrict__ outh,
                           float* sW, int nblocks) {
    for (int i = threadIdx.x; i < 3 * FDIM * FDIM / 4; i += 512)
        ((float4*)sW)[i] = ((const float4*)Wp)[i];
    __syncthreads();

    int rg = threadIdx.x >> 4;     // 0..31
    int q  = threadIdx.x & 15;     // 0..15
    int jb = q * 4;

    float bia[4];
#pragma unroll
    for (int j = 0; j < 4; j++) bia[j] = bias[jb + j];

    const int ntiles = (N_NODES + 127) / 128;
    for (int tile = blockIdx.x; tile < ntiles; tile += nblocks) {
        int r0 = tile * 128 + rg;           // rows r0 + 32*i, i = 0..3

        unsigned long long acc[8];
#pragma unroll
        for (int i = 0; i < 8; i++) acc[i] = 0ULL;

        for (int kk = 0; kk < FDIM; kk += 2) {
            float2       f0[4];
            unsigned int h1[4], h2[4];
#pragma unroll
            for (int i = 0; i < 4; i++) {
                int r = r0 + 32 * i;
                if (r < N_NODES) {
                    f0[i] = __ldg((const float2*)(t0 + r * FDIM + kk));
                    h1[i] = __ldg((const unsigned int*)(t1h + r * FDIM + kk));
                    h2[i] = __ldg((const unsigned int*)(p2h + r * FDIM + kk));
                } else {
                    f0[i] = make_float2(0.f, 0.f);
                    h1[i] = 0u; h2[i] = 0u;
                }
            }
#pragma unroll
            for (int u = 0; u < 2; u++) {
                int k = kk + u;
                ulonglong2 w0 = *(const ulonglong2*)(sW + k * FDIM + jb);
                ulonglong2 w1 = *(const ulonglong2*)(sW + 4096 + k * FDIM + jb);
                ulonglong2 w2 = *(const ulonglong2*)(sW + 8192 + k * FDIM + jb);
#pragma unroll
                for (int i = 0; i < 4; i++) {
                    float a0 = u ? f0[i].y : f0[i].x;
                    __half2 hh1 = *(__half2*)&h1[i];
                    __half2 hh2 = *(__half2*)&h2[i];
                    float a1 = u ? __high2float(hh1) : __low2float(hh1);
                    float a2 = u ? __high2float(hh2) : __low2float(hh2);
                    unsigned long long s0 = splat2(a0);
                    unsigned long long s1 = splat2(a1);
                    unsigned long long s2 = splat2(a2);
                    fma2(acc[2 * i],     w0.x, s0);
                    fma2(acc[2 * i + 1], w0.y, s0);
                    fma2(acc[2 * i],     w1.x, s1);
                    fma2(acc[2 * i + 1], w1.y, s1);
                    fma2(acc[2 * i],     w2.x, s2);
                    fma2(acc[2 * i + 1], w2.y, s2);
                }
            }
        }

#pragma unroll
        for (int i = 0; i < 4; i++) {
            int r = r0 + 32 * i;
            if (r >= N_NODES) break;
            float o[4];
            {
                float f0v, f1v;
                asm("mov.b64 {%0, %1}, %2;" : "=f"(f0v), "=f"(f1v)
                    : "l"(acc[2 * i]));
                o[0] = f0v; o[1] = f1v;
                asm("mov.b64 {%0, %1}, %2;" : "=f"(f0v), "=f"(f1v)
                    : "l"(acc[2 * i + 1]));
                o[2] = f0v; o[3] = f1v;
            }
            if (skip) {
                float4 sk = __ldg((const float4*)(skip + r * FDIM + jb));
                o[0] += sk.x; o[1] += sk.y; o[2] += sk.z; o[3] += sk.w;
            }
#pragma unroll
            for (int j = 0; j < 4; j++) o[j] = fmaxf(o[j] + bia[j], 0.f);
            *(float4*)(out32 + r * FDIM + jb) =
                make_float4(o[0], o[1], o[2], o[3]);
            if (outh) {
                uint2 pk;
                __half2 hh0 = __floats2half2_rn(o[0], o[1]);
                __half2 hh1 = __floats2half2_rn(o[2], o[3]);
                pk.x = *(unsigned int*)&hh0;
                pk.y = *(unsigned int*)&hh1;
                *(uint2*)(outh + r * FDIM + jb) = pk;
            }
        }
    }
}

// ---------------- launch 4: persistent fused prep+compute ---------------------
// Static smem must stay <= 48 KB: scan2 scratch overlaid on sW (consumed
// behind grid barriers before gemm_phase writes sW).
__global__ __launch_bounds__(512, 2) void fused_kernel(
    const float* __restrict__ x, const void* __restrict__ ei,
    const float* __restrict__ W, const float* __restrict__ b,
    float* __restrict__ out, int nblocks) {
    __shared__ float sW[3 * FDIM * FDIM];  // 48 KB (also scan2 scratch)
    int tid = threadIdx.x;
    int gtid = blockIdx.x * 512 + tid;
    int gstride = nblocks * 512;

    // ---- scan2 (block 0 only; scratch overlaid on sW) ----
    if (blockIdx.x == 0) {
        int* sh = (int*)sW;
        int v = 0;
        if (tid < 128) {
            v = (tid < NB_SCAN) ? g_bsum[tid] : 0;
            sh[tid] = v;
        }
        __syncthreads();
        for (int off = 1; off < 128; off <<= 1) {
            int t2 = 0;
            if (tid < 128 && tid >= off) t2 = sh[tid - off];
            __syncthreads();
            if (tid < 128) sh[tid] += t2;
            __syncthreads();
        }
        if (tid < NB_SCAN) g_bsum[tid] = sh[tid] - v;
        if (tid == 0) g_rowptr[N_NODES] = N_EDGES;
    }
    grid_barrier(nblocks);

    // ---- scan3: finalize rowptr + cursor ----
    for (int i = gtid; i < N_NODES; i += gstride) {
        int v = g_rowptr[i] + g_bsum[i >> 10];
        g_rowptr[i] = v;
        g_cursor[i] = v;
    }
    grid_barrier(nblocks);

    // ---- fill CSR + weight transform + x->fp16 ----
    int2* edges = (int2*)g_edge4;
    for (int e = gtid; e < N_EDGES; e += gstride) {
        int s, d;
        load_edge(ei, e, s, d);
        int pos = atomicAdd(&g_cursor[d], 1);
        int pd = g_degs[s] * g_degs[d];
        float nv = (pd > 0) ? -rsqrtf((float)pd) : 0.0f;
        edges[pos] = make_int2(s, __float_as_int(nv));
    }
    for (int i = gtid; i < 3 * 3 * 4096; i += gstride) {
        int layer = i / 12288, rem = i % 12288;
        int t = rem / 4096, idx = rem % 4096;
        const float* Wl = W + layer * 12288;
        float v;
        if (t == 0)      v = Wl[idx] - Wl[2 * 4096 + idx];
        else if (t == 1) v = Wl[4096 + idx];
        else             v = 2.0f * Wl[2 * 4096 + idx];
        g_Wp[layer][t * 4096 + idx] = v;
    }
    for (int i = gtid; i < N_NODES * FDIM / 4; i += gstride) {
        float4 v = __ldg((const float4*)x + i);
        __half2 h0 = __floats2half2_rn(v.x, v.y);
        __half2 h1 = __floats2half2_rn(v.z, v.w);
        uint2 pk;
        pk.x = *(unsigned int*)&h0;
        pk.y = *(unsigned int*)&h1;
        ((uint2*)g_xh)[i] = pk;
    }
    grid_barrier(nblocks);

    // ---- layer 0 ----
    pull_phase(g_xh, g_t1h, gtid, gstride);
    grid_barrier(nblocks);
    pull_phase(g_t1h, g_p2h, gtid, gstride);
    grid_barrier(nblocks);
    gemm_phase(x, g_t1h, g_p2h, g_Wp[0], b, nullptr, g_hA32, g_hAh, sW, nblocks);
    grid_barrier(nblocks);
    // ---- layer 1 ----
    pull_phase(g_hAh, g_t1h, gtid, gstride);
    grid_barrier(nblocks);
    pull_phase(g_t1h, g_p2h, gtid, gstride);
    grid_barrier(nblocks);
    gemm_phase(g_hA32, g_t1h, g_p2h, g_Wp[1], b + FDIM, g_hA32,
               g_hB32, g_hBh, sW, nblocks);
    grid_barrier(nblocks);
    // ---- layer 2 ----
    pull_phase(g_hBh, g_t1h, gtid, gstride);
    grid_barrier(nblocks);
    pull_phase(g_t1h, g_p2h, gtid, gstride);
    grid_barrier(nblocks);
    gemm_phase(g_hB32, g_t1h, g_p2h, g_Wp[2], b + 2 * FDIM, g_hB32,
               out, nullptr, sW, nblocks);
}

// ---------------- launch orchestration ---------------------------------------
static inline int cdiv(long long a, long long b) { return (int)((a + b - 1) / b); }

extern "C" void kernel_launch(void* const* d_in, const int* in_sizes, int n_in,
                              void* d_out, int out_size) {
    const float* x  = (const float*)d_in[0];
    const void*  ei = d_in[1];
    const float* W  = (const float*)d_in[2];
    const float* b  = (const float*)d_in[3];
    float*       out = (float*)d_out;

    // launches 1-3: init, degree count, per-chunk scan
    init_kernel<<<cdiv(N_NODES, 256), 256>>>((const int*)ei);
    count_kernel<<<cdiv(N_EDGES, 256), 256>>>(ei);
    scan1_kernel<<<NB_SCAN, 1024>>>();

    // launch 4: everything else, persistent + grid barriers
    int dev = 0, nsm = 148, nb_per_sm = 0;
    cudaGetDevice(&dev);
    cudaDeviceGetAttribute(&nsm, cudaDevAttrMultiProcessorCount, dev);
    cudaOccupancyMaxActiveBlocksPerMultiprocessor(&nb_per_sm, fused_kernel,
                                                  512, 0);
    if (nb_per_sm < 1) nb_per_sm = 1;
    int nblocks = nsm * nb_per_sm;
    fused_kernel<<<nblocks, 512>>>(x, ei, W, b, out, nblocks);
}

// round 12
// speedup vs baseline: 1.7548x; 1.0494x over previous
#include <cuda_runtime.h>
#include <cuda_fp16.h>

#define N_NODES 100000
#define N_EDGES 1200000
#define FDIM 64
#define NB_SCAN ((N_NODES + 1023) / 1024)   // 98
#define E_PAD (N_EDGES + 3 * N_NODES + 16)  // padded edge capacity

// ---------------- scratch (device globals; no allocation allowed) -------------
__device__ int      g_is64;
__device__ int      g_degs[N_NODES];
__device__ int      g_degd[N_NODES];
__device__ int      g_rowptr[N_NODES + 1];
__device__ int      g_cursor[N_NODES];
__device__ int      g_bsum[NB_SCAN];
__device__ int4     g_edge4[E_PAD / 2];      // (src,norm) pairs, 16B-aligned
__device__ __half   g_xh [N_NODES * FDIM];
__device__ __half   g_t1h[N_NODES * FDIM];
__device__ __half   g_p2h[N_NODES * FDIM];
__device__ __half   g_hAh[N_NODES * FDIM];
__device__ __half   g_hBh[N_NODES * FDIM];
__device__ float    g_hA32[N_NODES * FDIM];
__device__ float    g_hB32[N_NODES * FDIM];
__device__ float    g_Wp[3][3 * FDIM * FDIM];
__device__ unsigned g_bar_count;
__device__ unsigned g_bar_gen;

// ---------------- launch 1: zero degrees + dtype detect + barrier reset -------
__global__ void init_kernel(const int* __restrict__ ei32) {
    int i = blockIdx.x * blockDim.x + threadIdx.x;
    if (i < N_NODES) { g_degs[i] = 0; g_degd[i] = 0; }
    if (i == 0) {
        int odd_zero = 1;
        for (int k = 0; k < 512; k++)
            if (ei32[2 * k + 1] != 0) { odd_zero = 0; break; }
        g_is64 = odd_zero;
        g_bar_count = 0;
        g_bar_gen = 0;
    }
}

__device__ __forceinline__ void load_edge(const void* ei, int e, int& s, int& d) {
    if (g_is64) {
        const long long* p = (const long long*)ei;
        s = (int)p[e]; d = (int)p[N_EDGES + e];
    } else {
        const int* p = (const int*)ei;
        s = p[e]; d = p[N_EDGES + e];
    }
    if ((unsigned)s >= N_NODES || (unsigned)d >= N_NODES) { s = 0; d = 0; }
}

// ---------------- launch 2: degree histogram ----------------------------------
__global__ void count_kernel(const void* __restrict__ ei) {
    int e = blockIdx.x * blockDim.x + threadIdx.x;
    if (e >= N_EDGES) return;
    int s, d;
    load_edge(ei, e, s, d);
    atomicAdd(&g_degs[s], 1);
    atomicAdd(&g_degd[d], 1);
}

// ---------------- launch 3: per-block scan of PADDED in-degrees ---------------
__global__ __launch_bounds__(1024) void scan1_kernel() {
    __shared__ int s[1024];
    int tid = threadIdx.x;
    int i = blockIdx.x * 1024 + tid;
    int v = (i < N_NODES) ? ((g_degd[i] + 3) & ~3) : 0;
    s[tid] = v;
    __syncthreads();
    for (int off = 1; off < 1024; off <<= 1) {
        int t = (tid >= off) ? s[tid - off] : 0;
        __syncthreads();
        s[tid] += t;
        __syncthreads();
    }
    int incl = s[tid];
    if (i < N_NODES) g_rowptr[i] = incl - v;
    if (tid == 1023) g_bsum[blockIdx.x] = incl;
}

// ---------------- grid-wide software barrier ----------------------------------
__device__ __forceinline__ void grid_barrier(int nblocks) {
    __syncthreads();
    if (threadIdx.x == 0) {
        __threadfence();
        unsigned gen = *(volatile unsigned*)&g_bar_gen;
        unsigned t = atomicAdd(&g_bar_count, 1u);
        if (t == (unsigned)nblocks - 1u) {
            g_bar_count = 0u;
            __threadfence();
            atomicAdd(&g_bar_gen, 1u);
        } else {
            while (*(volatile unsigned*)&g_bar_gen == gen) __nanosleep(64);
        }
        __threadfence();
    }
    __syncthreads();
}

// ---------------- pull phase: out[n] = sum norm * in[src], fp16 rows ----------
// Padded CSR: every range is a multiple of 4, 4-aligned, padding entries have
// norm=0/src=0. No predication, no clamps; next quad prefetched unconditionally.
__device__ void pull_phase(const __half* __restrict__ in,
                           __half* __restrict__ out,
                           int gtid, int gstride) {
    for (int t = gtid; t < N_NODES * 8; t += gstride) {
        int node = t >> 3;
        int lane = t & 7;
        int e   = __ldg(&g_rowptr[node]);
        int end = __ldg(&g_rowptr[node + 1]);
        float acc[8];
#pragma unroll
        for (int j = 0; j < 8; j++) acc[j] = 0.f;

        if (e < end) {
            int4 qa = __ldg(&g_edge4[(e >> 1)]);
            int4 qb = __ldg(&g_edge4[(e >> 1) + 1]);
            while (true) {
                // unconditional prefetch (array over-padded by 8 entries)
                int4 na = __ldg(&g_edge4[(e >> 1) + 2]);
                int4 nb = __ldg(&g_edge4[(e >> 1) + 3]);
                uint4 v0 = __ldg((const uint4*)(in + qa.x * FDIM + lane * 8));
                uint4 v1 = __ldg((const uint4*)(in + qa.z * FDIM + lane * 8));
                uint4 v2 = __ldg((const uint4*)(in + qb.x * FDIM + lane * 8));
                uint4 v3 = __ldg((const uint4*)(in + qb.z * FDIM + lane * 8));
                float n0 = __int_as_float(qa.y), n1 = __int_as_float(qa.w);
                float n2 = __int_as_float(qb.y), n3 = __int_as_float(qb.w);
                const __half2* h0 = (const __half2*)&v0;
                const __half2* h1 = (const __half2*)&v1;
                const __half2* h2 = (const __half2*)&v2;
                const __half2* h3 = (const __half2*)&v3;
#pragma unroll
                for (int p = 0; p < 4; p++) {
                    float2 f0 = __half22float2(h0[p]);
                    float2 f1 = __half22float2(h1[p]);
                    float2 f2 = __half22float2(h2[p]);
                    float2 f3 = __half22float2(h3[p]);
                    acc[2*p]   = fmaf(n0, f0.x, acc[2*p]);
                    acc[2*p+1] = fmaf(n0, f0.y, acc[2*p+1]);
                    acc[2*p]   = fmaf(n1, f1.x, acc[2*p]);
                    acc[2*p+1] = fmaf(n1, f1.y, acc[2*p+1]);
                    acc[2*p]   = fmaf(n2, f2.x, acc[2*p]);
                    acc[2*p+1] = fmaf(n2, f2.y, acc[2*p+1]);
                    acc[2*p]   = fmaf(n3, f3.x, acc[2*p]);
                    acc[2*p+1] = fmaf(n3, f3.y, acc[2*p+1]);
                }
                e += 4;
                if (e >= end) break;
                qa = na; qb = nb;
            }
        }
        uint4 pk;
        __half2 ph0 = __floats2half2_rn(acc[0], acc[1]);
        __half2 ph1 = __floats2half2_rn(acc[2], acc[3]);
        __half2 ph2 = __floats2half2_rn(acc[4], acc[5]);
        __half2 ph3 = __floats2half2_rn(acc[6], acc[7]);
        pk.x = *(unsigned int*)&ph0; pk.y = *(unsigned int*)&ph1;
        pk.z = *(unsigned int*)&ph2; pk.w = *(unsigned int*)&ph3;
        *(uint4*)(out + node * FDIM + lane * 8) = pk;
    }
}

// ---------------- GEMM helpers -------------------------------------------------
__device__ __forceinline__ void fma2(unsigned long long& acc,
                                     unsigned long long w,
                                     unsigned long long a) {
    asm("fma.rn.f32x2 %0, %1, %2, %0;" : "+l"(acc) : "l"(w), "l"(a));
}
__device__ __forceinline__ unsigned long long splat2(float f) {
    unsigned long long r;
    asm("mov.b64 %0, {%1, %1};" : "=l"(r) : "f"(f));
    return r;
}

// GEMM phase: 512 threads = 32 row-slots x 16 j-groups (4 outputs each),
// 4 rows per thread (tile = 128 rows). 3 LDS.128 per k for 24 FMA2.
__device__ void gemm_phase(const float* __restrict__ t0,
                           const __half* __restrict__ t1h,
                           const __half* __restrict__ p2h,
                           const float* __restrict__ Wp,
                           const float* __restrict__ bias,
                           const float* __restrict__ skip,
                           float* __restrict__ out32,
                           __half* __restrict__ outh,
                           float* sW, int nblocks) {
    for (int i = threadIdx.x; i < 3 * FDIM * FDIM / 4; i += 512)
        ((float4*)sW)[i] = ((const float4*)Wp)[i];
    __syncthreads();

    int rg = threadIdx.x >> 4;     // 0..31
    int q  = threadIdx.x & 15;     // 0..15
    int jb = q * 4;

    float bia[4];
#pragma unroll
    for (int j = 0; j < 4; j++) bia[j] = bias[jb + j];

    const int ntiles = (N_NODES + 127) / 128;
    for (int tile = blockIdx.x; tile < ntiles; tile += nblocks) {
        int r0 = tile * 128 + rg;

        unsigned long long acc[8];
#pragma unroll
        for (int i = 0; i < 8; i++) acc[i] = 0ULL;

        for (int kk = 0; kk < FDIM; kk += 2) {
            float2       f0[4];
            unsigned int h1[4], h2[4];
#pragma unroll
            for (int i = 0; i < 4; i++) {
                int r = r0 + 32 * i;
                if (r < N_NODES) {
                    f0[i] = __ldg((const float2*)(t0 + r * FDIM + kk));
                    h1[i] = __ldg((const unsigned int*)(t1h + r * FDIM + kk));
                    h2[i] = __ldg((const unsigned int*)(p2h + r * FDIM + kk));
                } else {
                    f0[i] = make_float2(0.f, 0.f);
                    h1[i] = 0u; h2[i] = 0u;
                }
            }
#pragma unroll
            for (int u = 0; u < 2; u++) {
                int k = kk + u;
                ulonglong2 w0 = *(const ulonglong2*)(sW + k * FDIM + jb);
                ulonglong2 w1 = *(const ulonglong2*)(sW + 4096 + k * FDIM + jb);
                ulonglong2 w2 = *(const ulonglong2*)(sW + 8192 + k * FDIM + jb);
#pragma unroll
                for (int i = 0; i < 4; i++) {
                    float a0 = u ? f0[i].y : f0[i].x;
                    __half2 hh1 = *(__half2*)&h1[i];
                    __half2 hh2 = *(__half2*)&h2[i];
                    float a1 = u ? __high2float(hh1) : __low2float(hh1);
                    float a2 = u ? __high2float(hh2) : __low2float(hh2);
                    unsigned long long s0 = splat2(a0);
                    unsigned long long s1 = splat2(a1);
                    unsigned long long s2 = splat2(a2);
                    fma2(acc[2 * i],     w0.x, s0);
                    fma2(acc[2 * i + 1], w0.y, s0);
                    fma2(acc[2 * i],     w1.x, s1);
                    fma2(acc[2 * i + 1], w1.y, s1);
                    fma2(acc[2 * i],     w2.x, s2);
                    fma2(acc[2 * i + 1], w2.y, s2);
                }
            }
        }

#pragma unroll
        for (int i = 0; i < 4; i++) {
            int r = r0 + 32 * i;
            if (r >= N_NODES) break;
            float o[4];
            {
                float f0v, f1v;
                asm("mov.b64 {%0, %1}, %2;" : "=f"(f0v), "=f"(f1v)
                    : "l"(acc[2 * i]));
                o[0] = f0v; o[1] = f1v;
                asm("mov.b64 {%0, %1}, %2;" : "=f"(f0v), "=f"(f1v)
                    : "l"(acc[2 * i + 1]));
                o[2] = f0v; o[3] = f1v;
            }
            if (skip) {
                float4 sk = __ldg((const float4*)(skip + r * FDIM + jb));
                o[0] += sk.x; o[1] += sk.y; o[2] += sk.z; o[3] += sk.w;
            }
#pragma unroll
            for (int j = 0; j < 4; j++) o[j] = fmaxf(o[j] + bia[j], 0.f);
            *(float4*)(out32 + r * FDIM + jb) =
                make_float4(o[0], o[1], o[2], o[3]);
            if (outh) {
                uint2 pk;
                __half2 hh0 = __floats2half2_rn(o[0], o[1]);
                __half2 hh1 = __floats2half2_rn(o[2], o[3]);
                pk.x = *(unsigned int*)&hh0;
                pk.y = *(unsigned int*)&hh1;
                *(uint2*)(outh + r * FDIM + jb) = pk;
            }
        }
    }
}

// ---------------- launch 4: persistent fused prep+compute ---------------------
__global__ __launch_bounds__(512, 2) void fused_kernel(
    const float* __restrict__ x, const void* __restrict__ ei,
    const float* __restrict__ W, const float* __restrict__ b,
    float* __restrict__ out, int nblocks) {
    __shared__ float sW[3 * FDIM * FDIM];  // 48 KB (also scan2 scratch)
    int tid = threadIdx.x;
    int gtid = blockIdx.x * 512 + tid;
    int gstride = nblocks * 512;

    // ---- scan2 (block 0 only; scratch overlaid on sW) ----
    if (blockIdx.x == 0) {
        int* sh = (int*)sW;
        int v = 0;
        if (tid < 128) {
            v = (tid < NB_SCAN) ? g_bsum[tid] : 0;
            sh[tid] = v;
        }
        __syncthreads();
        for (int off = 1; off < 128; off <<= 1) {
            int t2 = 0;
            if (tid < 128 && tid >= off) t2 = sh[tid - off];
            __syncthreads();
            if (tid < 128) sh[tid] += t2;
            __syncthreads();
        }
        if (tid < NB_SCAN) {
            g_bsum[tid] = sh[tid] - v;
            if (tid == NB_SCAN - 1) g_rowptr[N_NODES] = sh[tid];  // padded total
        }
    }
    grid_barrier(nblocks);

    // ---- scan3: finalize rowptr + cursor ----
    for (int i = gtid; i < N_NODES; i += gstride) {
        int v = g_rowptr[i] + g_bsum[i >> 10];
        g_rowptr[i] = v;
        g_cursor[i] = v;
    }
    grid_barrier(nblocks);

    // ---- fill CSR + padding + weight transform + x->fp16 ----
    int2* edges = (int2*)g_edge4;
    for (int e = gtid; e < N_EDGES; e += gstride) {
        int s, d;
        load_edge(ei, e, s, d);
        int pos = atomicAdd(&g_cursor[d], 1);
        int pd = g_degs[s] * g_degs[d];
        float nv = (pd > 0) ? -rsqrtf((float)pd) : 0.0f;
        edges[pos] = make_int2(s, __float_as_int(nv));
    }
    // padding slots: [rowptr[i] + degd[i], rowptr[i+1]) get (src=0, norm=0)
    for (int i = gtid; i < N_NODES; i += gstride) {
        int p0 = g_rowptr[i] + g_degd[i];
        int p1 = g_rowptr[i + 1];
        for (int p = p0; p < p1; p++) edges[p] = make_int2(0, 0);
    }
    for (int i = gtid; i < 3 * 3 * 4096; i += gstride) {
        int layer = i / 12288, rem = i % 12288;
        int t = rem / 4096, idx = rem % 4096;
        const float* Wl = W + layer * 12288;
        float v;
        if (t == 0)      v = Wl[idx] - Wl[2 * 4096 + idx];
        else if (t == 1) v = Wl[4096 + idx];
        else             v = 2.0f * Wl[2 * 4096 + idx];
        g_Wp[layer][t * 4096 + idx] = v;
    }
    for (int i = gtid; i < N_NODES * FDIM / 4; i += gstride) {
        float4 v = __ldg((const float4*)x + i);
        __half2 h0 = __floats2half2_rn(v.x, v.y);
        __half2 h1 = __floats2half2_rn(v.z, v.w);
        uint2 pk;
        pk.x = *(unsigned int*)&h0;
        pk.y = *(unsigned int*)&h1;
        ((uint2*)g_xh)[i] = pk;
    }
    grid_barrier(nblocks);

    // ---- layer 0 ----
    pull_phase(g_xh, g_t1h, gtid, gstride);
    grid_barrier(nblocks);
    pull_phase(g_t1h, g_p2h, gtid, gstride);
    grid_barrier(nblocks);
    gemm_phase(x, g_t1h, g_p2h, g_Wp[0], b, nullptr, g_hA32, g_hAh, sW, nblocks);
    grid_barrier(nblocks);
    // ---- layer 1 ----
    pull_phase(g_hAh, g_t1h, gtid, gstride);
    grid_barrier(nblocks);
    pull_phase(g_t1h, g_p2h, gtid, gstride);
    grid_barrier(nblocks);
    gemm_phase(g_hA32, g_t1h, g_p2h, g_Wp[1], b + FDIM, g_hA32,
               g_hB32, g_hBh, sW, nblocks);
    grid_barrier(nblocks);
    // ---- layer 2 ----
    pull_phase(g_hBh, g_t1h, gtid, gstride);
    grid_barrier(nblocks);
    pull_phase(g_t1h, g_p2h, gtid, gstride);
    grid_barrier(nblocks);
    gemm_phase(g_hB32, g_t1h, g_p2h, g_Wp[2], b + 2 * FDIM, g_hB32,
               out, nullptr, sW, nblocks);
}

// ---------------- launch orchestration ---------------------------------------
static inline int cdiv(long long a, long long b) { return (int)((a + b - 1) / b); }

extern "C" void kernel_launch(void* const* d_in, const int* in_sizes, int n_in,
                              void* d_out, int out_size) {
    const float* x  = (const float*)d_in[0];
    const void*  ei = d_in[1];
    const float* W  = (const float*)d_in[2];
    const float* b  = (const float*)d_in[3];
    float*       out = (float*)d_out;

    init_kernel<<<cdiv(N_NODES, 256), 256>>>((const int*)ei);
    count_kernel<<<cdiv(N_EDGES, 256), 256>>>(ei);
    scan1_kernel<<<NB_SCAN, 1024>>>();

    int dev = 0, nsm = 148, nb_per_sm = 0;
    cudaGetDevice(&dev);
    cudaDeviceGetAttribute(&nsm, cudaDevAttrMultiProcessorCount, dev);
    cudaOccupancyMaxActiveBlocksPerMultiprocessor(&nb_per_sm, fused_kernel,
                                                  512, 0);
    if (nb_per_sm < 1) nb_per_sm = 1;
    int nblocks = nsm * nb_per_sm;
    fused_kernel<<<nblocks, 512>>>(x, ei, W, b, out, nblocks);
}

// round 13
// speedup vs baseline: 1.7883x; 1.0191x over previous
#include <cuda_runtime.h>
#include <cuda_fp16.h>

#define N_NODES 100000
#define N_EDGES 1200000
#define FDIM 64
#define NB_SCAN ((N_NODES + 1023) / 1024)   // 98
#define E_PAD (N_EDGES + 3 * N_NODES + 16)  // padded edge capacity

// ---------------- scratch (device globals; no allocation allowed) -------------
__device__ int      g_is64;
__device__ int      g_degs[N_NODES];
__device__ int      g_degd[N_NODES];
__device__ int      g_rowptr[N_NODES + 1];
__device__ int      g_cursor[N_NODES];
__device__ int      g_bsum[NB_SCAN];
__device__ int4     g_edge4[E_PAD / 2];      // (src,norm) pairs, 16B-aligned
__device__ __half   g_xh [N_NODES * FDIM];
__device__ __half   g_t1h[N_NODES * FDIM];
__device__ __half   g_p2h[N_NODES * FDIM];
__device__ __half   g_hAh[N_NODES * FDIM];
__device__ __half   g_hBh[N_NODES * FDIM];
__device__ float    g_Wp[3][3 * FDIM * FDIM];
__device__ unsigned g_bar_count;
__device__ unsigned g_bar_gen;

// ---------------- launch 1: zero degrees + dtype detect + barrier reset -------
__global__ void init_kernel(const int* __restrict__ ei32) {
    int i = blockIdx.x * blockDim.x + threadIdx.x;
    if (i < N_NODES) { g_degs[i] = 0; g_degd[i] = 0; }
    if (i == 0) {
        int odd_zero = 1;
        for (int k = 0; k < 512; k++)
            if (ei32[2 * k + 1] != 0) { odd_zero = 0; break; }
        g_is64 = odd_zero;
        g_bar_count = 0;
        g_bar_gen = 0;
    }
}

__device__ __forceinline__ void load_edge(const void* ei, int e, int& s, int& d) {
    if (g_is64) {
        const long long* p = (const long long*)ei;
        s = (int)p[e]; d = (int)p[N_EDGES + e];
    } else {
        const int* p = (const int*)ei;
        s = p[e]; d = p[N_EDGES + e];
    }
    if ((unsigned)s >= N_NODES || (unsigned)d >= N_NODES) { s = 0; d = 0; }
}

// ---------------- launch 2: degree histogram ----------------------------------
__global__ void count_kernel(const void* __restrict__ ei) {
    int e = blockIdx.x * blockDim.x + threadIdx.x;
    if (e >= N_EDGES) return;
    int s, d;
    load_edge(ei, e, s, d);
    atomicAdd(&g_degs[s], 1);
    atomicAdd(&g_degd[d], 1);
}

// ---------------- launch 3: per-block scan of PADDED in-degrees ---------------
__global__ __launch_bounds__(1024) void scan1_kernel() {
    __shared__ int s[1024];
    int tid = threadIdx.x;
    int i = blockIdx.x * 1024 + tid;
    int v = (i < N_NODES) ? ((g_degd[i] + 3) & ~3) : 0;
    s[tid] = v;
    __syncthreads();
    for (int off = 1; off < 1024; off <<= 1) {
        int t = (tid >= off) ? s[tid - off] : 0;
        __syncthreads();
        s[tid] += t;
        __syncthreads();
    }
    int incl = s[tid];
    if (i < N_NODES) g_rowptr[i] = incl - v;
    if (tid == 1023) g_bsum[blockIdx.x] = incl;
}

// ---------------- grid-wide software barrier ----------------------------------
__device__ __forceinline__ void grid_barrier(int nblocks) {
    __syncthreads();
    if (threadIdx.x == 0) {
        __threadfence();
        unsigned gen = *(volatile unsigned*)&g_bar_gen;
        unsigned t = atomicAdd(&g_bar_count, 1u);
        if (t == (unsigned)nblocks - 1u) {
            g_bar_count = 0u;
            __threadfence();
            atomicAdd(&g_bar_gen, 1u);
        } else {
            while (*(volatile unsigned*)&g_bar_gen == gen) __nanosleep(64);
        }
        __threadfence();
    }
    __syncthreads();
}

// ---------------- pull phase: out[n] = sum norm * in[src], fp16 rows ----------
// Padded CSR: every range multiple of 4, aligned; padding entries norm=0/src=0.
__device__ void pull_phase(const __half* __restrict__ in,
                           __half* __restrict__ out,
                           int gtid, int gstride) {
    for (int t = gtid; t < N_NODES * 8; t += gstride) {
        int node = t >> 3;
        int lane = t & 7;
        int e   = __ldg(&g_rowptr[node]);
        int end = __ldg(&g_rowptr[node + 1]);
        float acc[8];
#pragma unroll
        for (int j = 0; j < 8; j++) acc[j] = 0.f;

        if (e < end) {
            int4 qa = __ldg(&g_edge4[(e >> 1)]);
            int4 qb = __ldg(&g_edge4[(e >> 1) + 1]);
            while (true) {
                int4 na = __ldg(&g_edge4[(e >> 1) + 2]);
                int4 nb = __ldg(&g_edge4[(e >> 1) + 3]);
                uint4 v0 = __ldg((const uint4*)(in + qa.x * FDIM + lane * 8));
                uint4 v1 = __ldg((const uint4*)(in + qa.z * FDIM + lane * 8));
                uint4 v2 = __ldg((const uint4*)(in + qb.x * FDIM + lane * 8));
                uint4 v3 = __ldg((const uint4*)(in + qb.z * FDIM + lane * 8));
                float n0 = __int_as_float(qa.y), n1 = __int_as_float(qa.w);
                float n2 = __int_as_float(qb.y), n3 = __int_as_float(qb.w);
                const __half2* h0 = (const __half2*)&v0;
                const __half2* h1 = (const __half2*)&v1;
                const __half2* h2 = (const __half2*)&v2;
                const __half2* h3 = (const __half2*)&v3;
#pragma unroll
                for (int p = 0; p < 4; p++) {
                    float2 f0 = __half22float2(h0[p]);
                    float2 f1 = __half22float2(h1[p]);
                    float2 f2 = __half22float2(h2[p]);
                    float2 f3 = __half22float2(h3[p]);
                    acc[2*p]   = fmaf(n0, f0.x, acc[2*p]);
                    acc[2*p+1] = fmaf(n0, f0.y, acc[2*p+1]);
                    acc[2*p]   = fmaf(n1, f1.x, acc[2*p]);
                    acc[2*p+1] = fmaf(n1, f1.y, acc[2*p+1]);
                    acc[2*p]   = fmaf(n2, f2.x, acc[2*p]);
                    acc[2*p+1] = fmaf(n2, f2.y, acc[2*p+1]);
                    acc[2*p]   = fmaf(n3, f3.x, acc[2*p]);
                    acc[2*p+1] = fmaf(n3, f3.y, acc[2*p+1]);
                }
                e += 4;
                if (e >= end) break;
                qa = na; qb = nb;
            }
        }
        uint4 pk;
        __half2 ph0 = __floats2half2_rn(acc[0], acc[1]);
        __half2 ph1 = __floats2half2_rn(acc[2], acc[3]);
        __half2 ph2 = __floats2half2_rn(acc[4], acc[5]);
        __half2 ph3 = __floats2half2_rn(acc[6], acc[7]);
        pk.x = *(unsigned int*)&ph0; pk.y = *(unsigned int*)&ph1;
        pk.z = *(unsigned int*)&ph2; pk.w = *(unsigned int*)&ph3;
        *(uint4*)(out + node * FDIM + lane * 8) = pk;
    }
}

// ---------------- GEMM helpers -------------------------------------------------
__device__ __forceinline__ void fma2(unsigned long long& acc,
                                     unsigned long long w,
                                     unsigned long long a) {
    asm("fma.rn.f32x2 %0, %1, %2, %0;" : "+l"(acc) : "l"(w), "l"(a));
}
__device__ __forceinline__ unsigned long long splat2(float f) {
    unsigned long long r;
    asm("mov.b64 %0, {%1, %1};" : "=l"(r) : "f"(f));
    return r;
}

// GEMM phase: 512 threads = 32 row-slots x 16 j-groups (4 outputs each),
// 4 rows per thread. ALL inputs fp16 (t0h/t1h/p2h/skiph); fp32 accumulate.
// outh for intermediate layers, out32 for the final layer.
__device__ void gemm_phase(const __half* __restrict__ t0h,
                           const __half* __restrict__ t1h,
                           const __half* __restrict__ p2h,
                           const float* __restrict__ Wp,
                           const float* __restrict__ bias,
                           const __half* __restrict__ skiph,
                           float* __restrict__ out32,
                           __half* __restrict__ outh,
                           float* sW, int nblocks) {
    for (int i = threadIdx.x; i < 3 * FDIM * FDIM / 4; i += 512)
        ((float4*)sW)[i] = ((const float4*)Wp)[i];
    __syncthreads();

    int rg = threadIdx.x >> 4;     // 0..31
    int q  = threadIdx.x & 15;     // 0..15
    int jb = q * 4;

    float bia[4];
#pragma unroll
    for (int j = 0; j < 4; j++) bia[j] = bias[jb + j];

    const int ntiles = (N_NODES + 127) / 128;
    for (int tile = blockIdx.x; tile < ntiles; tile += nblocks) {
        int r0 = tile * 128 + rg;

        unsigned long long acc[8];
#pragma unroll
        for (int i = 0; i < 8; i++) acc[i] = 0ULL;

        for (int kk = 0; kk < FDIM; kk += 2) {
            unsigned int h0[4], h1[4], h2[4];
#pragma unroll
            for (int i = 0; i < 4; i++) {
                int r = r0 + 32 * i;
                if (r < N_NODES) {
                    h0[i] = __ldg((const unsigned int*)(t0h + r * FDIM + kk));
                    h1[i] = __ldg((const unsigned int*)(t1h + r * FDIM + kk));
                    h2[i] = __ldg((const unsigned int*)(p2h + r * FDIM + kk));
                } else {
                    h0[i] = 0u; h1[i] = 0u; h2[i] = 0u;
                }
            }
#pragma unroll
            for (int u = 0; u < 2; u++) {
                int k = kk + u;
                ulonglong2 w0 = *(const ulonglong2*)(sW + k * FDIM + jb);
                ulonglong2 w1 = *(const ulonglong2*)(sW + 4096 + k * FDIM + jb);
                ulonglong2 w2 = *(const ulonglong2*)(sW + 8192 + k * FDIM + jb);
#pragma unroll
                for (int i = 0; i < 4; i++) {
                    __half2 hh0 = *(__half2*)&h0[i];
                    __half2 hh1 = *(__half2*)&h1[i];
                    __half2 hh2 = *(__half2*)&h2[i];
                    float a0 = u ? __high2float(hh0) : __low2float(hh0);
                    float a1 = u ? __high2float(hh1) : __low2float(hh1);
                    float a2 = u ? __high2float(hh2) : __low2float(hh2);
                    unsigned long long s0 = splat2(a0);
                    unsigned long long s1 = splat2(a1);
                    unsigned long long s2 = splat2(a2);
                    fma2(acc[2 * i],     w0.x, s0);
                    fma2(acc[2 * i + 1], w0.y, s0);
                    fma2(acc[2 * i],     w1.x, s1);
                    fma2(acc[2 * i + 1], w1.y, s1);
                    fma2(acc[2 * i],     w2.x, s2);
                    fma2(acc[2 * i + 1], w2.y, s2);
                }
            }
        }

#pragma unroll
        for (int i = 0; i < 4; i++) {
            int r = r0 + 32 * i;
            if (r >= N_NODES) break;
            float o[4];
            {
                float f0v, f1v;
                asm("mov.b64 {%0, %1}, %2;" : "=f"(f0v), "=f"(f1v)
                    : "l"(acc[2 * i]));
                o[0] = f0v; o[1] = f1v;
                asm("mov.b64 {%0, %1}, %2;" : "=f"(f0v), "=f"(f1v)
                    : "l"(acc[2 * i + 1]));
                o[2] = f0v; o[3] = f1v;
            }
            if (skiph) {
                uint2 sk = __ldg((const uint2*)(skiph + r * FDIM + jb));
                float2 s0 = __half22float2(*(__half2*)&sk.x);
                float2 s1 = __half22float2(*(__half2*)&sk.y);
                o[0] += s0.x; o[1] += s0.y; o[2] += s1.x; o[3] += s1.y;
            }
#pragma unroll
            for (int j = 0; j < 4; j++) o[j] = fmaxf(o[j] + bia[j], 0.f);
            if (out32)
                *(float4*)(out32 + r * FDIM + jb) =
                    make_float4(o[0], o[1], o[2], o[3]);
            if (outh) {
                uint2 pk;
                __half2 hh0 = __floats2half2_rn(o[0], o[1]);
                __half2 hh1 = __floats2half2_rn(o[2], o[3]);
                pk.x = *(unsigned int*)&hh0;
                pk.y = *(unsigned int*)&hh1;
                *(uint2*)(outh + r * FDIM + jb) = pk;
            }
        }
    }
}

// ---------------- launch 4: persistent fused prep+compute ---------------------
__global__ __launch_bounds__(512, 2) void fused_kernel(
    const float* __restrict__ x, const void* __restrict__ ei,
    const float* __restrict__ W, const float* __restrict__ b,
    float* __restrict__ out, int nblocks) {
    __shared__ float sW[3 * FDIM * FDIM];  // 48 KB (also scan2 scratch)
    int tid = threadIdx.x;
    int gtid = blockIdx.x * 512 + tid;
    int gstride = nblocks * 512;

    // ---- scan2 (block 0 only; scratch overlaid on sW) ----
    if (blockIdx.x == 0) {
        int* sh = (int*)sW;
        int v = 0;
        if (tid < 128) {
            v = (tid < NB_SCAN) ? g_bsum[tid] : 0;
            sh[tid] = v;
        }
        __syncthreads();
        for (int off = 1; off < 128; off <<= 1) {
            int t2 = 0;
            if (tid < 128 && tid >= off) t2 = sh[tid - off];
            __syncthreads();
            if (tid < 128) sh[tid] += t2;
            __syncthreads();
        }
        if (tid < NB_SCAN) {
            g_bsum[tid] = sh[tid] - v;
            if (tid == NB_SCAN - 1) g_rowptr[N_NODES] = sh[tid];  // padded total
        }
    }
    grid_barrier(nblocks);

    // ---- scan3: finalize rowptr + cursor ----
    for (int i = gtid; i < N_NODES; i += gstride) {
        int v = g_rowptr[i] + g_bsum[i >> 10];
        g_rowptr[i] = v;
        g_cursor[i] = v;
    }
    grid_barrier(nblocks);

    // ---- fill CSR + padding + weight transform + x->fp16 ----
    int2* edges = (int2*)g_edge4;
    for (int e = gtid; e < N_EDGES; e += gstride) {
        int s, d;
        load_edge(ei, e, s, d);
        int pos = atomicAdd(&g_cursor[d], 1);
        int pd = g_degs[s] * g_degs[d];
        float nv = (pd > 0) ? -rsqrtf((float)pd) : 0.0f;
        edges[pos] = make_int2(s, __float_as_int(nv));
    }
    for (int i = gtid; i < N_NODES; i += gstride) {
        int p0 = g_rowptr[i] + g_degd[i];
        int p1 = g_rowptr[i + 1];
        for (int p = p0; p < p1; p++) edges[p] = make_int2(0, 0);
    }
    for (int i = gtid; i < 3 * 3 * 4096; i += gstride) {
        int layer = i / 12288, rem = i % 12288;
        int t = rem / 4096, idx = rem % 4096;
        const float* Wl = W + layer * 12288;
        float v;
        if (t == 0)      v = Wl[idx] - Wl[2 * 4096 + idx];
        else if (t == 1) v = Wl[4096 + idx];
        else             v = 2.0f * Wl[2 * 4096 + idx];
        g_Wp[layer][t * 4096 + idx] = v;
    }
    for (int i = gtid; i < N_NODES * FDIM / 4; i += gstride) {
        float4 v = __ldg((const float4*)x + i);
        __half2 h0 = __floats2half2_rn(v.x, v.y);
        __half2 h1 = __floats2half2_rn(v.z, v.w);
        uint2 pk;
        pk.x = *(unsigned int*)&h0;
        pk.y = *(unsigned int*)&h1;
        ((uint2*)g_xh)[i] = pk;
    }
    grid_barrier(nblocks);

    // ---- layer 0 ----
    pull_phase(g_xh, g_t1h, gtid, gstride);
    grid_barrier(nblocks);
    pull_phase(g_t1h, g_p2h, gtid, gstride);
    grid_barrier(nblocks);
    gemm_phase(g_xh, g_t1h, g_p2h, g_Wp[0], b, nullptr,
               nullptr, g_hAh, sW, nblocks);
    grid_barrier(nblocks);
    // ---- layer 1 ----
    pull_phase(g_hAh, g_t1h, gtid, gstride);
    grid_barrier(nblocks);
    pull_phase(g_t1h, g_p2h, gtid, gstride);
    grid_barrier(nblocks);
    gemm_phase(g_hAh, g_t1h, g_p2h, g_Wp[1], b + FDIM, g_hAh,
               nullptr, g_hBh, sW, nblocks);
    grid_barrier(nblocks);
    // ---- layer 2 ----
    pull_phase(g_hBh, g_t1h, gtid, gstride);
    grid_barrier(nblocks);
    pull_phase(g_t1h, g_p2h, gtid, gstride);
    grid_barrier(nblocks);
    gemm_phase(g_hBh, g_t1h, g_p2h, g_Wp[2], b + 2 * FDIM, g_hBh,
               out, nullptr, sW, nblocks);
}

// ---------------- launch orchestration ---------------------------------------
static inline int cdiv(long long a, long long b) { return (int)((a + b - 1) / b); }

extern "C" void kernel_launch(void* const* d_in, const int* in_sizes, int n_in,
                              void* d_out, int out_size) {
    const float* x  = (const float*)d_in[0];
    const void*  ei = d_in[1];
    const float* W  = (const float*)d_in[2];
    const float* b  = (const float*)d_in[3];
    float*       out = (float*)d_out;

    init_kernel<<<cdiv(N_NODES, 256), 256>>>((const int*)ei);
    count_kernel<<<cdiv(N_EDGES, 256), 256>>>(ei);
    scan1_kernel<<<NB_SCAN, 1024>>>();

    int dev = 0, nsm = 148, nb_per_sm = 0;
    cudaGetDevice(&dev);
    cudaDeviceGetAttribute(&nsm, cudaDevAttrMultiProcessorCount, dev);
    cudaOccupancyMaxActiveBlocksPerMultiprocessor(&nb_per_sm, fused_kernel,
                                                  512, 0);
    if (nb_per_sm < 1) nb_per_sm = 1;
    int nblocks = nsm * nb_per_sm;
    fused_kernel<<<nblocks, 512>>>(x, ei, W, b, out, nblocks);
}

// round 14
// speedup vs baseline: 3.0991x; 1.7330x over previous
#include <cuda_runtime.h>
#include <cuda_fp16.h>

#define N_NODES 100000
#define N_EDGES 1200000
#define FDIM 64
#define KDIM 192                            // 3 * FDIM (concat t0|t1|p2)
#define NB_SCAN ((N_NODES + 1023) / 1024)   // 98
#define E_PAD (N_EDGES + 3 * N_NODES + 16)  // padded edge capacity

// smem layout (dynamic): fp16 weights [192][72], then act tile [64][200]
#define WS 72                                // weight row stride (halves)
#define AS 200                               // act row stride (halves)
#define SMEM_W_BYTES (KDIM * WS * 2)         // 27648
#define SMEM_ACT_OFF SMEM_W_BYTES
#define SMEM_TOTAL (SMEM_W_BYTES + 64 * AS * 2)  // 53248

// ---------------- scratch (device globals; no allocation allowed) -------------
__device__ int      g_is64;
__device__ int      g_degs[N_NODES];
__device__ int      g_degd[N_NODES];
__device__ int      g_rowptr[N_NODES + 1];
__device__ int      g_cursor[N_NODES];
__device__ int      g_bsum[NB_SCAN];
__device__ int4     g_edge4[E_PAD / 2];
__device__ __half   g_xh [N_NODES * FDIM];
__device__ __half   g_t1h[N_NODES * FDIM];
__device__ __half   g_p2h[N_NODES * FDIM];
__device__ __half   g_hAh[N_NODES * FDIM];
__device__ __half   g_hBh[N_NODES * FDIM];
__device__ float    g_Wp[3][KDIM * FDIM];   // transformed weights, [192][64] f32
__device__ unsigned g_bar_count;
__device__ unsigned g_bar_gen;

// ---------------- launch 1 ----------------------------------------------------
__global__ void init_kernel(const int* __restrict__ ei32) {
    int i = blockIdx.x * blockDim.x + threadIdx.x;
    if (i < N_NODES) { g_degs[i] = 0; g_degd[i] = 0; }
    if (i == 0) {
        int odd_zero = 1;
        for (int k = 0; k < 512; k++)
            if (ei32[2 * k + 1] != 0) { odd_zero = 0; break; }
        g_is64 = odd_zero;
        g_bar_count = 0;
        g_bar_gen = 0;
    }
}

__device__ __forceinline__ void load_edge(const void* ei, int e, int& s, int& d) {
    if (g_is64) {
        const long long* p = (const long long*)ei;
        s = (int)p[e]; d = (int)p[N_EDGES + e];
    } else {
        const int* p = (const int*)ei;
        s = p[e]; d = p[N_EDGES + e];
    }
    if ((unsigned)s >= N_NODES || (unsigned)d >= N_NODES) { s = 0; d = 0; }
}

// ---------------- launch 2 ----------------------------------------------------
__global__ void count_kernel(const void* __restrict__ ei) {
    int e = blockIdx.x * blockDim.x + threadIdx.x;
    if (e >= N_EDGES) return;
    int s, d;
    load_edge(ei, e, s, d);
    atomicAdd(&g_degs[s], 1);
    atomicAdd(&g_degd[d], 1);
}

// ---------------- launch 3: per-block scan of PADDED in-degrees ---------------
__global__ __launch_bounds__(1024) void scan1_kernel() {
    __shared__ int s[1024];
    int tid = threadIdx.x;
    int i = blockIdx.x * 1024 + tid;
    int v = (i < N_NODES) ? ((g_degd[i] + 3) & ~3) : 0;
    s[tid] = v;
    __syncthreads();
    for (int off = 1; off < 1024; off <<= 1) {
        int t = (tid >= off) ? s[tid - off] : 0;
        __syncthreads();
        s[tid] += t;
        __syncthreads();
    }
    int incl = s[tid];
    if (i < N_NODES) g_rowptr[i] = incl - v;
    if (tid == 1023) g_bsum[blockIdx.x] = incl;
}

// ---------------- grid-wide software barrier ----------------------------------
__device__ __forceinline__ void grid_barrier(int nblocks) {
    __syncthreads();
    if (threadIdx.x == 0) {
        __threadfence();
        unsigned gen = *(volatile unsigned*)&g_bar_gen;
        unsigned t = atomicAdd(&g_bar_count, 1u);
        if (t == (unsigned)nblocks - 1u) {
            g_bar_count = 0u;
            __threadfence();
            atomicAdd(&g_bar_gen, 1u);
        } else {
            while (*(volatile unsigned*)&g_bar_gen == gen) __nanosleep(64);
        }
        __threadfence();
    }
    __syncthreads();
}

// ---------------- pull phase (unchanged from R13) ------------------------------
__device__ void pull_phase(const __half* __restrict__ in,
                           __half* __restrict__ out,
                           int gtid, int gstride) {
    for (int t = gtid; t < N_NODES * 8; t += gstride) {
        int node = t >> 3;
        int lane = t & 7;
        int e   = __ldg(&g_rowptr[node]);
        int end = __ldg(&g_rowptr[node + 1]);
        float acc[8];
#pragma unroll
        for (int j = 0; j < 8; j++) acc[j] = 0.f;

        if (e < end) {
            int4 qa = __ldg(&g_edge4[(e >> 1)]);
            int4 qb = __ldg(&g_edge4[(e >> 1) + 1]);
            while (true) {
                int4 na = __ldg(&g_edge4[(e >> 1) + 2]);
                int4 nb = __ldg(&g_edge4[(e >> 1) + 3]);
                uint4 v0 = __ldg((const uint4*)(in + qa.x * FDIM + lane * 8));
                uint4 v1 = __ldg((const uint4*)(in + qa.z * FDIM + lane * 8));
                uint4 v2 = __ldg((const uint4*)(in + qb.x * FDIM + lane * 8));
                uint4 v3 = __ldg((const uint4*)(in + qb.z * FDIM + lane * 8));
                float n0 = __int_as_float(qa.y), n1 = __int_as_float(qa.w);
                float n2 = __int_as_float(qb.y), n3 = __int_as_float(qb.w);
                const __half2* h0 = (const __half2*)&v0;
                const __half2* h1 = (const __half2*)&v1;
                const __half2* h2 = (const __half2*)&v2;
                const __half2* h3 = (const __half2*)&v3;
#pragma unroll
                for (int p = 0; p < 4; p++) {
                    float2 f0 = __half22float2(h0[p]);
                    float2 f1 = __half22float2(h1[p]);
                    float2 f2 = __half22float2(h2[p]);
                    float2 f3 = __half22float2(h3[p]);
                    acc[2*p]   = fmaf(n0, f0.x, acc[2*p]);
                    acc[2*p+1] = fmaf(n0, f0.y, acc[2*p+1]);
                    acc[2*p]   = fmaf(n1, f1.x, acc[2*p]);
                    acc[2*p+1] = fmaf(n1, f1.y, acc[2*p+1]);
                    acc[2*p]   = fmaf(n2, f2.x, acc[2*p]);
                    acc[2*p+1] = fmaf(n2, f2.y, acc[2*p+1]);
                    acc[2*p]   = fmaf(n3, f3.x, acc[2*p]);
                    acc[2*p+1] = fmaf(n3, f3.y, acc[2*p+1]);
                }
                e += 4;
                if (e >= end) break;
                qa = na; qb = nb;
            }
        }
        uint4 pk;
        __half2 ph0 = __floats2half2_rn(acc[0], acc[1]);
        __half2 ph1 = __floats2half2_rn(acc[2], acc[3]);
        __half2 ph2 = __floats2half2_rn(acc[4], acc[5]);
        __half2 ph3 = __floats2half2_rn(acc[6], acc[7]);
        pk.x = *(unsigned int*)&ph0; pk.y = *(unsigned int*)&ph1;
        pk.z = *(unsigned int*)&ph2; pk.w = *(unsigned int*)&ph3;
        *(uint4*)(out + node * FDIM + lane * 8) = pk;
    }
}

// ---------------- tensor-core GEMM phase --------------------------------------
__device__ __forceinline__ unsigned s2u(const void* p) {
    return (unsigned)__cvta_generic_to_shared(p);
}

// out[r,0:64] = relu( [t0|t1|p2][r,0:192] * Wh[192,64] + bias (+skip) )
// tile = 64 rows; 16 warps: warp w -> m-chunk (w>>2)*16, n-chunk (w&3)*16.
__device__ void gemm_phase(const __half* __restrict__ t0h,
                           const __half* __restrict__ t1h,
                           const __half* __restrict__ p2h,
                           const float* __restrict__ Wp,
                           const float* __restrict__ bias,
                           const __half* __restrict__ skiph,
                           float* __restrict__ out32,
                           __half* __restrict__ outh,
                           char* smem, int nblocks) {
    __half* sWh  = (__half*)smem;                    // [192][WS]
    __half* sAct = (__half*)(smem + SMEM_ACT_OFF);   // [64][AS]

    // load + cvt weights (fp32 -> fp16), [192][64] contiguous in Wp
    for (int i = threadIdx.x; i < KDIM * FDIM / 2; i += 512) {
        int idx = i * 2;
        int row = idx >> 6, col = idx & 63;
        float2 w = *(const float2*)(Wp + idx);
        *(__half2*)(sWh + row * WS + col) = __floats2half2_rn(w.x, w.y);
    }
    __syncthreads();

    int tid  = threadIdx.x;
    int lane = tid & 31;
    int w    = tid >> 5;          // 0..15
    int mrow  = (w >> 2) * 16;
    int nbase = (w & 3) * 16;
    int g  = lane >> 2;           // groupID
    int tg = lane & 3;

    // ldmatrix source addresses (byte offsets advance with kbase)
    unsigned aAddr0 = s2u(sAct + (mrow + (lane & 15)) * AS + ((lane >> 4) << 3));
    unsigned bAddr0 = s2u(sWh + (lane & 15) * WS + nbase + ((lane >> 4) << 3));

    const int ntiles = (N_NODES + 63) / 64;
    for (int tile = blockIdx.x; tile < ntiles; tile += nblocks) {
        int tb = tile * 64;

        // stage activation tile: 64 rows x [t0|t1|p2] into sAct
        for (int i = tid; i < 64 * 24; i += 512) {
            int row = i / 24, c = i % 24;
            int arr = c >> 3, off = (c & 7) * 8;
            int r = tb + row;
            uint4 v = make_uint4(0u, 0u, 0u, 0u);
            if (r < N_NODES) {
                const __half* src = (arr == 0) ? t0h : (arr == 1) ? t1h : p2h;
                v = __ldg((const uint4*)(src + r * FDIM + off));
            }
            *(uint4*)(sAct + row * AS + arr * 64 + off) = v;
        }
        __syncthreads();

        float d0[4] = {0.f, 0.f, 0.f, 0.f};
        float d1[4] = {0.f, 0.f, 0.f, 0.f};
#pragma unroll
        for (int ks = 0; ks < KDIM / 16; ks++) {
            unsigned a0, a1, a2, a3, b0, b1, b2, b3;
            asm volatile(
                "ldmatrix.sync.aligned.m8n8.x4.shared.b16 {%0,%1,%2,%3}, [%4];"
                : "=r"(a0), "=r"(a1), "=r"(a2), "=r"(a3)
                : "r"(aAddr0 + ks * 32));
            asm volatile(
                "ldmatrix.sync.aligned.m8n8.x4.trans.shared.b16 {%0,%1,%2,%3}, [%4];"
                : "=r"(b0), "=r"(b1), "=r"(b2), "=r"(b3)
                : "r"(bAddr0 + ks * (16 * WS * 2)));
            asm volatile(
                "mma.sync.aligned.m16n8k16.row.col.f32.f16.f16.f32 "
                "{%0,%1,%2,%3}, {%4,%5,%6,%7}, {%8,%9}, {%0,%1,%2,%3};"
                : "+f"(d0[0]), "+f"(d0[1]), "+f"(d0[2]), "+f"(d0[3])
                : "r"(a0), "r"(a1), "r"(a2), "r"(a3), "r"(b0), "r"(b1));
            asm volatile(
                "mma.sync.aligned.m16n8k16.row.col.f32.f16.f16.f32 "
                "{%0,%1,%2,%3}, {%4,%5,%6,%7}, {%8,%9}, {%0,%1,%2,%3};"
                : "+f"(d1[0]), "+f"(d1[1]), "+f"(d1[2]), "+f"(d1[3])
                : "r"(a0), "r"(a1), "r"(a2), "r"(a3), "r"(b2), "r"(b3));
        }

        // epilogue: d0 -> cols nbase+tg*2, d1 -> cols nbase+8+tg*2
#pragma unroll
        for (int j = 0; j < 2; j++) {
            float* d = j ? d1 : d0;
            int col = nbase + j * 8 + tg * 2;
            float2 bi = __ldg((const float2*)(bias + col));
#pragma unroll
            for (int i = 0; i < 2; i++) {
                int r = tb + mrow + g + i * 8;
                if (r >= N_NODES) continue;
                float v0 = d[2 * i] + bi.x;
                float v1 = d[2 * i + 1] + bi.y;
                if (skiph) {
                    unsigned sk = __ldg((const unsigned*)(skiph + r * FDIM + col));
                    float2 sf = __half22float2(*(__half2*)&sk);
                    v0 += sf.x; v1 += sf.y;
                }
                v0 = fmaxf(v0, 0.f);
                v1 = fmaxf(v1, 0.f);
                if (out32)
                    *(float2*)(out32 + r * FDIM + col) = make_float2(v0, v1);
                if (outh) {
                    __half2 hh = __floats2half2_rn(v0, v1);
                    *(unsigned*)(outh + r * FDIM + col) = *(unsigned*)&hh;
                }
            }
        }
        __syncthreads();   // before next tile overwrites sAct
    }
}

// ---------------- launch 4: persistent fused prep+compute ---------------------
__global__ __launch_bounds__(512, 2) void fused_kernel(
    const float* __restrict__ x, const void* __restrict__ ei,
    const float* __restrict__ W, const float* __restrict__ b,
    float* __restrict__ out, int nblocks) {
    extern __shared__ char smem[];
    int tid = threadIdx.x;
    int gtid = blockIdx.x * 512 + tid;
    int gstride = nblocks * 512;

    // ---- scan2 (block 0 only; scratch overlaid on smem) ----
    if (blockIdx.x == 0) {
        int* sh = (int*)smem;
        int v = 0;
        if (tid < 128) {
            v = (tid < NB_SCAN) ? g_bsum[tid] : 0;
            sh[tid] = v;
        }
        __syncthreads();
        for (int off = 1; off < 128; off <<= 1) {
            int t2 = 0;
            if (tid < 128 && tid >= off) t2 = sh[tid - off];
            __syncthreads();
            if (tid < 128) sh[tid] += t2;
            __syncthreads();
        }
        if (tid < NB_SCAN) {
            g_bsum[tid] = sh[tid] - v;
            if (tid == NB_SCAN - 1) g_rowptr[N_NODES] = sh[tid];
        }
    }
    grid_barrier(nblocks);

    // ---- scan3 ----
    for (int i = gtid; i < N_NODES; i += gstride) {
        int v = g_rowptr[i] + g_bsum[i >> 10];
        g_rowptr[i] = v;
        g_cursor[i] = v;
    }
    grid_barrier(nblocks);

    // ---- fill CSR + padding + weight transform + x->fp16 ----
    int2* edges = (int2*)g_edge4;
    for (int e = gtid; e < N_EDGES; e += gstride) {
        int s, d;
        load_edge(ei, e, s, d);
        int pos = atomicAdd(&g_cursor[d], 1);
        int pd = g_degs[s] * g_degs[d];
        float nv = (pd > 0) ? -rsqrtf((float)pd) : 0.0f;
        edges[pos] = make_int2(s, __float_as_int(nv));
    }
    for (int i = gtid; i < N_NODES; i += gstride) {
        int p0 = g_rowptr[i] + g_degd[i];
        int p1 = g_rowptr[i + 1];
        for (int p = p0; p < p1; p++) edges[p] = make_int2(0, 0);
    }
    for (int i = gtid; i < 3 * 3 * 4096; i += gstride) {
        int layer = i / 12288, rem = i % 12288;
        int t = rem / 4096, idx = rem % 4096;
        const float* Wl = W + layer * 12288;
        float v;
        if (t == 0)      v = Wl[idx] - Wl[2 * 4096 + idx];
        else if (t == 1) v = Wl[4096 + idx];
        else             v = 2.0f * Wl[2 * 4096 + idx];
        g_Wp[layer][t * 4096 + idx] = v;
    }
    for (int i = gtid; i < N_NODES * FDIM / 4; i += gstride) {
        float4 v = __ldg((const float4*)x + i);
        __half2 h0 = __floats2half2_rn(v.x, v.y);
        __half2 h1 = __floats2half2_rn(v.z, v.w);
        uint2 pk;
        pk.x = *(unsigned int*)&h0;
        pk.y = *(unsigned int*)&h1;
        ((uint2*)g_xh)[i] = pk;
    }
    grid_barrier(nblocks);

    // ---- layer 0 ----
    pull_phase(g_xh, g_t1h, gtid, gstride);
    grid_barrier(nblocks);
    pull_phase(g_t1h, g_p2h, gtid, gstride);
    grid_barrier(nblocks);
    gemm_phase(g_xh, g_t1h, g_p2h, g_Wp[0], b, nullptr,
               nullptr, g_hAh, smem, nblocks);
    grid_barrier(nblocks);
    // ---- layer 1 ----
    pull_phase(g_hAh, g_t1h, gtid, gstride);
    grid_barrier(nblocks);
    pull_phase(g_t1h, g_p2h, gtid, gstride);
    grid_barrier(nblocks);
    gemm_phase(g_hAh, g_t1h, g_p2h, g_Wp[1], b + FDIM, g_hAh,
               nullptr, g_hBh, smem, nblocks);
    grid_barrier(nblocks);
    // ---- layer 2 ----
    pull_phase(g_hBh, g_t1h, gtid, gstride);
    grid_barrier(nblocks);
    pull_phase(g_t1h, g_p2h, gtid, gstride);
    grid_barrier(nblocks);
    gemm_phase(g_hBh, g_t1h, g_p2h, g_Wp[2], b + 2 * FDIM, g_hBh,
               out, nullptr, smem, nblocks);
}

// ---------------- launch orchestration ---------------------------------------
static inline int cdiv(long long a, long long b) { return (int)((a + b - 1) / b); }

extern "C" void kernel_launch(void* const* d_in, const int* in_sizes, int n_in,
                              void* d_out, int out_size) {
    const float* x  = (const float*)d_in[0];
    const void*  ei = d_in[1];
    const float* W  = (const float*)d_in[2];
    const float* b  = (const float*)d_in[3];
    float*       out = (float*)d_out;

    init_kernel<<<cdiv(N_NODES, 256), 256>>>((const int*)ei);
    count_kernel<<<cdiv(N_EDGES, 256), 256>>>(ei);
    scan1_kernel<<<NB_SCAN, 1024>>>();

    cudaFuncSetAttribute(fused_kernel,
                         cudaFuncAttributeMaxDynamicSharedMemorySize,
                         SMEM_TOTAL);
    int dev = 0, nsm = 148, nb_per_sm = 0;
    cudaGetDevice(&dev);
    cudaDeviceGetAttribute(&nsm, cudaDevAttrMultiProcessorCount, dev);
    cudaOccupancyMaxActiveBlocksPerMultiprocessor(&nb_per_sm, fused_kernel,
                                                  512, SMEM_TOTAL);
    if (nb_per_sm < 1) nb_per_sm = 1;
    int nblocks = nsm * nb_per_sm;
    fused_kernel<<<nblocks, 512, SMEM_TOTAL>>>(x, ei, W, b, out, nblocks);
}

// round 15
// speedup vs baseline: 3.1612x; 1.0200x over previous
#include <cuda_runtime.h>
#include <cuda_fp16.h>

#define N_NODES 100000
#define N_EDGES 1200000
#define FDIM 64
#define KDIM 192                            // 3 * FDIM (concat t0|t1|p2)
#define NB_SCAN ((N_NODES + 1023) / 1024)   // 98
#define E_PAD (N_EDGES + 3 * N_NODES + 16)  // padded edge capacity

// smem layout (dynamic): fp16 weights [192][72], then act tile [64][200]
#define WS 72                                // weight row stride (halves)
#define AS 200                               // act row stride (halves)
#define SMEM_W_BYTES (KDIM * WS * 2)         // 27648
#define SMEM_ACT_OFF SMEM_W_BYTES
#define SMEM_TOTAL (SMEM_W_BYTES + 64 * AS * 2)  // 53248

// ---------------- scratch (device globals; no allocation allowed) -------------
__device__ int      g_is64;
__device__ int      g_degs[N_NODES];
__device__ int      g_degd[N_NODES];
__device__ int      g_rowptr[N_NODES + 1];
__device__ int      g_cursor[N_NODES];
__device__ int      g_bsum[NB_SCAN];
__device__ int4     g_edge4[E_PAD / 2];
__device__ __half   g_xh [N_NODES * FDIM];
__device__ __half   g_t1h[N_NODES * FDIM];
__device__ __half   g_p2h[N_NODES * FDIM];
__device__ __half   g_hAh[N_NODES * FDIM];
__device__ __half   g_hBh[N_NODES * FDIM];
__device__ float    g_Wp[3][KDIM * FDIM];   // transformed weights, [192][64] f32
__device__ unsigned g_bar_count;
__device__ unsigned g_bar_gen;

// ---------------- launch 1 ----------------------------------------------------
__global__ void init_kernel(const int* __restrict__ ei32) {
    int i = blockIdx.x * blockDim.x + threadIdx.x;
    if (i < N_NODES) { g_degs[i] = 0; g_degd[i] = 0; }
    if (i == 0) {
        int odd_zero = 1;
        for (int k = 0; k < 512; k++)
            if (ei32[2 * k + 1] != 0) { odd_zero = 0; break; }
        g_is64 = odd_zero;
        g_bar_count = 0;
        g_bar_gen = 0;
    }
}

__device__ __forceinline__ void load_edge(const void* ei, int e, int& s, int& d) {
    if (g_is64) {
        const long long* p = (const long long*)ei;
        s = (int)p[e]; d = (int)p[N_EDGES + e];
    } else {
        const int* p = (const int*)ei;
        s = p[e]; d = p[N_EDGES + e];
    }
    if ((unsigned)s >= N_NODES || (unsigned)d >= N_NODES) { s = 0; d = 0; }
}

// ---------------- launch 2 ----------------------------------------------------
__global__ void count_kernel(const void* __restrict__ ei) {
    int e = blockIdx.x * blockDim.x + threadIdx.x;
    if (e >= N_EDGES) return;
    int s, d;
    load_edge(ei, e, s, d);
    atomicAdd(&g_degs[s], 1);
    atomicAdd(&g_degd[d], 1);
}

// ---------------- launch 3: per-block scan of PADDED in-degrees ---------------
__global__ __launch_bounds__(1024) void scan1_kernel() {
    __shared__ int s[1024];
    int tid = threadIdx.x;
    int i = blockIdx.x * 1024 + tid;
    int v = (i < N_NODES) ? ((g_degd[i] + 3) & ~3) : 0;
    s[tid] = v;
    __syncthreads();
    for (int off = 1; off < 1024; off <<= 1) {
        int t = (tid >= off) ? s[tid - off] : 0;
        __syncthreads();
        s[tid] += t;
        __syncthreads();
    }
    int incl = s[tid];
    if (i < N_NODES) g_rowptr[i] = incl - v;
    if (tid == 1023) g_bsum[blockIdx.x] = incl;
}

// ---------------- grid-wide software barrier ----------------------------------
__device__ __forceinline__ void grid_barrier(int nblocks) {
    __syncthreads();
    if (threadIdx.x == 0) {
        __threadfence();
        unsigned gen = *(volatile unsigned*)&g_bar_gen;
        unsigned t = atomicAdd(&g_bar_count, 1u);
        if (t == (unsigned)nblocks - 1u) {
            g_bar_count = 0u;
            __threadfence();
            atomicAdd(&g_bar_gen, 1u);
        } else {
            while (*(volatile unsigned*)&g_bar_gen == gen) __nanosleep(64);
        }
        __threadfence();
    }
    __syncthreads();
}

// ---------------- pull phase (unchanged) ---------------------------------------
__device__ void pull_phase(const __half* __restrict__ in,
                           __half* __restrict__ out,
                           int gtid, int gstride) {
    for (int t = gtid; t < N_NODES * 8; t += gstride) {
        int node = t >> 3;
        int lane = t & 7;
        int e   = __ldg(&g_rowptr[node]);
        int end = __ldg(&g_rowptr[node + 1]);
        float acc[8];
#pragma unroll
        for (int j = 0; j < 8; j++) acc[j] = 0.f;

        if (e < end) {
            int4 qa = __ldg(&g_edge4[(e >> 1)]);
            int4 qb = __ldg(&g_edge4[(e >> 1) + 1]);
            while (true) {
                int4 na = __ldg(&g_edge4[(e >> 1) + 2]);
                int4 nb = __ldg(&g_edge4[(e >> 1) + 3]);
                uint4 v0 = __ldg((const uint4*)(in + qa.x * FDIM + lane * 8));
                uint4 v1 = __ldg((const uint4*)(in + qa.z * FDIM + lane * 8));
                uint4 v2 = __ldg((const uint4*)(in + qb.x * FDIM + lane * 8));
                uint4 v3 = __ldg((const uint4*)(in + qb.z * FDIM + lane * 8));
                float n0 = __int_as_float(qa.y), n1 = __int_as_float(qa.w);
                float n2 = __int_as_float(qb.y), n3 = __int_as_float(qb.w);
                const __half2* h0 = (const __half2*)&v0;
                const __half2* h1 = (const __half2*)&v1;
                const __half2* h2 = (const __half2*)&v2;
                const __half2* h3 = (const __half2*)&v3;
#pragma unroll
                for (int p = 0; p < 4; p++) {
                    float2 f0 = __half22float2(h0[p]);
                    float2 f1 = __half22float2(h1[p]);
                    float2 f2 = __half22float2(h2[p]);
                    float2 f3 = __half22float2(h3[p]);
                    acc[2*p]   = fmaf(n0, f0.x, acc[2*p]);
                    acc[2*p+1] = fmaf(n0, f0.y, acc[2*p+1]);
                    acc[2*p]   = fmaf(n1, f1.x, acc[2*p]);
                    acc[2*p+1] = fmaf(n1, f1.y, acc[2*p+1]);
                    acc[2*p]   = fmaf(n2, f2.x, acc[2*p]);
                    acc[2*p+1] = fmaf(n2, f2.y, acc[2*p+1]);
                    acc[2*p]   = fmaf(n3, f3.x, acc[2*p]);
                    acc[2*p+1] = fmaf(n3, f3.y, acc[2*p+1]);
                }
                e += 4;
                if (e >= end) break;
                qa = na; qb = nb;
            }
        }
        uint4 pk;
        __half2 ph0 = __floats2half2_rn(acc[0], acc[1]);
        __half2 ph1 = __floats2half2_rn(acc[2], acc[3]);
        __half2 ph2 = __floats2half2_rn(acc[4], acc[5]);
        __half2 ph3 = __floats2half2_rn(acc[6], acc[7]);
        pk.x = *(unsigned int*)&ph0; pk.y = *(unsigned int*)&ph1;
        pk.z = *(unsigned int*)&ph2; pk.w = *(unsigned int*)&ph3;
        *(uint4*)(out + node * FDIM + lane * 8) = pk;
    }
}

// ---------------- tensor-core GEMM phase --------------------------------------
__device__ __forceinline__ unsigned s2u(const void* p) {
    return (unsigned)__cvta_generic_to_shared(p);
}

__device__ void gemm_phase(const __half* __restrict__ t0h,
                           const __half* __restrict__ t1h,
                           const __half* __restrict__ p2h,
                           const float* __restrict__ Wp,
                           const float* __restrict__ bias,
                           const __half* __restrict__ skiph,
                           float* __restrict__ out32,
                           __half* __restrict__ outh,
                           char* smem, int nblocks) {
    __half* sWh  = (__half*)smem;                    // [192][WS]
    __half* sAct = (__half*)(smem + SMEM_ACT_OFF);   // [64][AS]

    for (int i = threadIdx.x; i < KDIM * FDIM / 2; i += 512) {
        int idx = i * 2;
        int row = idx >> 6, col = idx & 63;
        float2 w = *(const float2*)(Wp + idx);
        *(__half2*)(sWh + row * WS + col) = __floats2half2_rn(w.x, w.y);
    }
    __syncthreads();

    int tid  = threadIdx.x;
    int lane = tid & 31;
    int w    = tid >> 5;          // 0..15
    int mrow  = (w >> 2) * 16;
    int nbase = (w & 3) * 16;
    int g  = lane >> 2;
    int tg = lane & 3;

    unsigned aAddr0 = s2u(sAct + (mrow + (lane & 15)) * AS + ((lane >> 4) << 3));
    unsigned bAddr0 = s2u(sWh + (lane & 15) * WS + nbase + ((lane >> 4) << 3));

    const int ntiles = (N_NODES + 63) / 64;
    for (int tile = blockIdx.x; tile < ntiles; tile += nblocks) {
        int tb = tile * 64;

        for (int i = tid; i < 64 * 24; i += 512) {
            int row = i / 24, c = i % 24;
            int arr = c >> 3, off = (c & 7) * 8;
            int r = tb + row;
            uint4 v = make_uint4(0u, 0u, 0u, 0u);
            if (r < N_NODES) {
                const __half* src = (arr == 0) ? t0h : (arr == 1) ? t1h : p2h;
                v = __ldg((const uint4*)(src + r * FDIM + off));
            }
            *(uint4*)(sAct + row * AS + arr * 64 + off) = v;
        }
        __syncthreads();

        float d0[4] = {0.f, 0.f, 0.f, 0.f};
        float d1[4] = {0.f, 0.f, 0.f, 0.f};
#pragma unroll
        for (int ks = 0; ks < KDIM / 16; ks++) {
            unsigned a0, a1, a2, a3, b0, b1, b2, b3;
            asm volatile(
                "ldmatrix.sync.aligned.m8n8.x4.shared.b16 {%0,%1,%2,%3}, [%4];"
                : "=r"(a0), "=r"(a1), "=r"(a2), "=r"(a3)
                : "r"(aAddr0 + ks * 32));
            asm volatile(
                "ldmatrix.sync.aligned.m8n8.x4.trans.shared.b16 {%0,%1,%2,%3}, [%4];"
                : "=r"(b0), "=r"(b1), "=r"(b2), "=r"(b3)
                : "r"(bAddr0 + ks * (16 * WS * 2)));
            asm volatile(
                "mma.sync.aligned.m16n8k16.row.col.f32.f16.f16.f32 "
                "{%0,%1,%2,%3}, {%4,%5,%6,%7}, {%8,%9}, {%0,%1,%2,%3};"
                : "+f"(d0[0]), "+f"(d0[1]), "+f"(d0[2]), "+f"(d0[3])
                : "r"(a0), "r"(a1), "r"(a2), "r"(a3), "r"(b0), "r"(b1));
            asm volatile(
                "mma.sync.aligned.m16n8k16.row.col.f32.f16.f16.f32 "
                "{%0,%1,%2,%3}, {%4,%5,%6,%7}, {%8,%9}, {%0,%1,%2,%3};"
                : "+f"(d1[0]), "+f"(d1[1]), "+f"(d1[2]), "+f"(d1[3])
                : "r"(a0), "r"(a1), "r"(a2), "r"(a3), "r"(b2), "r"(b3));
        }

#pragma unroll
        for (int j = 0; j < 2; j++) {
            float* d = j ? d1 : d0;
            int col = nbase + j * 8 + tg * 2;
            float2 bi = __ldg((const float2*)(bias + col));
#pragma unroll
            for (int i = 0; i < 2; i++) {
                int r = tb + mrow + g + i * 8;
                if (r >= N_NODES) continue;
                float v0 = d[2 * i] + bi.x;
                float v1 = d[2 * i + 1] + bi.y;
                if (skiph) {
                    unsigned sk = __ldg((const unsigned*)(skiph + r * FDIM + col));
                    float2 sf = __half22float2(*(__half2*)&sk);
                    v0 += sf.x; v1 += sf.y;
                }
                v0 = fmaxf(v0, 0.f);
                v1 = fmaxf(v1, 0.f);
                if (out32)
                    *(float2*)(out32 + r * FDIM + col) = make_float2(v0, v1);
                if (outh) {
                    __half2 hh = __floats2half2_rn(v0, v1);
                    *(unsigned*)(outh + r * FDIM + col) = *(unsigned*)&hh;
                }
            }
        }
        __syncthreads();
    }
}

// ---------------- launch 4: persistent fused prep+compute ---------------------
__global__ __launch_bounds__(512, 3) void fused_kernel(
    const float* __restrict__ x, const void* __restrict__ ei,
    const float* __restrict__ W, const float* __restrict__ b,
    float* __restrict__ out, int nblocks) {
    extern __shared__ char smem[];
    int tid = threadIdx.x;
    int gtid = blockIdx.x * 512 + tid;
    int gstride = nblocks * 512;

    // ---- scan2 (block 0 only; scratch overlaid on smem) ----
    if (blockIdx.x == 0) {
        int* sh = (int*)smem;
        int v = 0;
        if (tid < 128) {
            v = (tid < NB_SCAN) ? g_bsum[tid] : 0;
            sh[tid] = v;
        }
        __syncthreads();
        for (int off = 1; off < 128; off <<= 1) {
            int t2 = 0;
            if (tid < 128 && tid >= off) t2 = sh[tid - off];
            __syncthreads();
            if (tid < 128) sh[tid] += t2;
            __syncthreads();
        }
        if (tid < NB_SCAN) {
            g_bsum[tid] = sh[tid] - v;
            if (tid == NB_SCAN - 1) g_rowptr[N_NODES] = sh[tid];
        }
    }
    grid_barrier(nblocks);

    // ---- scan3 ----
    for (int i = gtid; i < N_NODES; i += gstride) {
        int v = g_rowptr[i] + g_bsum[i >> 10];
        g_rowptr[i] = v;
        g_cursor[i] = v;
    }
    grid_barrier(nblocks);

    // ---- fill CSR + padding + weight transform + x->fp16 ----
    int2* edges = (int2*)g_edge4;
    for (int e = gtid; e < N_EDGES; e += gstride) {
        int s, d;
        load_edge(ei, e, s, d);
        int pos = atomicAdd(&g_cursor[d], 1);
        int pd = g_degs[s] * g_degs[d];
        float nv = (pd > 0) ? -rsqrtf((float)pd) : 0.0f;
        edges[pos] = make_int2(s, __float_as_int(nv));
    }
    for (int i = gtid; i < N_NODES; i += gstride) {
        int p0 = g_rowptr[i] + g_degd[i];
        int p1 = g_rowptr[i + 1];
        for (int p = p0; p < p1; p++) edges[p] = make_int2(0, 0);
    }
    for (int i = gtid; i < 3 * 3 * 4096; i += gstride) {
        int layer = i / 12288, rem = i % 12288;
        int t = rem / 4096, idx = rem % 4096;
        const float* Wl = W + layer * 12288;
        float v;
        if (t == 0)      v = Wl[idx] - Wl[2 * 4096 + idx];
        else if (t == 1) v = Wl[4096 + idx];
        else             v = 2.0f * Wl[2 * 4096 + idx];
        g_Wp[layer][t * 4096 + idx] = v;
    }
    for (int i = gtid; i < N_NODES * FDIM / 4; i += gstride) {
        float4 v = __ldg((const float4*)x + i);
        __half2 h0 = __floats2half2_rn(v.x, v.y);
        __half2 h1 = __floats2half2_rn(v.z, v.w);
        uint2 pk;
        pk.x = *(unsigned int*)&h0;
        pk.y = *(unsigned int*)&h1;
        ((uint2*)g_xh)[i] = pk;
    }
    grid_barrier(nblocks);

    // ---- layer 0 ----
    pull_phase(g_xh, g_t1h, gtid, gstride);
    grid_barrier(nblocks);
    pull_phase(g_t1h, g_p2h, gtid, gstride);
    grid_barrier(nblocks);
    gemm_phase(g_xh, g_t1h, g_p2h, g_Wp[0], b, nullptr,
               nullptr, g_hAh, smem, nblocks);
    grid_barrier(nblocks);
    // ---- layer 1 ----
    pull_phase(g_hAh, g_t1h, gtid, gstride);
    grid_barrier(nblocks);
    pull_phase(g_t1h, g_p2h, gtid, gstride);
    grid_barrier(nblocks);
    gemm_phase(g_hAh, g_t1h, g_p2h, g_Wp[1], b + FDIM, g_hAh,
               nullptr, g_hBh, smem, nblocks);
    grid_barrier(nblocks);
    // ---- layer 2 ----
    pull_phase(g_hBh, g_t1h, gtid, gstride);
    grid_barrier(nblocks);
    pull_phase(g_t1h, g_p2h, gtid, gstride);
    grid_barrier(nblocks);
    gemm_phase(g_hBh, g_t1h, g_p2h, g_Wp[2], b + 2 * FDIM, g_hBh,
               out, nullptr, smem, nblocks);
}

// ---------------- launch orchestration ---------------------------------------
static inline int cdiv(long long a, long long b) { return (int)((a + b - 1) / b); }

extern "C" void kernel_launch(void* const* d_in, const int* in_sizes, int n_in,
                              void* d_out, int out_size) {
    const float* x  = (const float*)d_in[0];
    const void*  ei = d_in[1];
    const float* W  = (const float*)d_in[2];
    const float* b  = (const float*)d_in[3];
    float*       out = (float*)d_out;

    init_kernel<<<cdiv(N_NODES, 256), 256>>>((const int*)ei);
    count_kernel<<<cdiv(N_EDGES, 256), 256>>>(ei);
    scan1_kernel<<<NB_SCAN, 1024>>>();

    cudaFuncSetAttribute(fused_kernel,
                         cudaFuncAttributeMaxDynamicSharedMemorySize,
                         SMEM_TOTAL);
    int dev = 0, nsm = 148, nb_per_sm = 0;
    cudaGetDevice(&dev);
    cudaDeviceGetAttribute(&nsm, cudaDevAttrMultiProcessorCount, dev);
    cudaOccupancyMaxActiveBlocksPerMultiprocessor(&nb_per_sm, fused_kernel,
                                                  512, SMEM_TOTAL);
    if (nb_per_sm < 1) nb_per_sm = 1;
    int nblocks = nsm * nb_per_sm;
    fused_kernel<<<nblocks, 512, SMEM_TOTAL>>>(x, ei, W, b, out, nblocks);
}